// round 1
// baseline (speedup 1.0000x reference)
#include <cuda_runtime.h>
#include <math.h>

// ---------------------------------------------------------------------------
// DifferentialAttention, algebraically folded:
//   qkv  = x @ Wqkv + bqkv                       [4096,1024]
//   M    = Wv @ Wo                               [512,512]   (K=8192)
//   V'   = x @ M                                 [4096,512]
//   l1   = Q1 @ K1^T * 0.125 ; l2 = Q2 @ K2^T * 0.125      [2][2048,2048]
//   diff = softmax(l1) - lam*softmax(l2)         (in place over l1)
//   out  = diff @ V' + (1-lam)*(bv@Wo) + bo      [2][2048,512]
// ---------------------------------------------------------------------------

#define BM 128
#define BN 128
#define BK 16
#define NTHREADS 256

// Scratch (static device memory; no allocations allowed)
__device__ float g_qkv[4096 * 1024];
__device__ float g_M[512 * 512];
__device__ float g_Vp[4096 * 512];
__device__ float g_l1[2 * 2048 * 2048];
__device__ float g_l2[2 * 2048 * 2048];
__device__ float g_lambda;
__device__ float g_cvec[512];

// ---------------------------------------------------------------------------
// Generic tiled SGEMM: C = alpha * A@B (+bias[n]), optional B-transpose.
// Assumes M%128==0, N%128==0, K%16==0, all lds %4==0 (true for all our shapes).
// ---------------------------------------------------------------------------
template <bool TB>
__global__ __launch_bounds__(NTHREADS) void sgemm_kernel(
    const float* __restrict__ A, const float* __restrict__ B,
    float* __restrict__ C,
    int M, int N, int K, int lda, int ldb, int ldc,
    long long sA, long long sB, long long sC,
    float alpha, const float* __restrict__ bias)
{
    A += (long long)blockIdx.z * sA;
    B += (long long)blockIdx.z * sB;
    C += (long long)blockIdx.z * sC;

    const int brow = blockIdx.y * BM;
    const int bcol = blockIdx.x * BN;
    const int t  = threadIdx.x;
    const int tx = t & 15;       // 0..15  -> column group (8 cols)
    const int ty = t >> 4;       // 0..15  -> row group (8 rows)

    __shared__ float As[BK][BM];
    __shared__ float Bs[BK][BN + 4];

    float acc[8][8];
#pragma unroll
    for (int i = 0; i < 8; i++)
#pragma unroll
        for (int j = 0; j < 8; j++) acc[i][j] = 0.f;

    // A-tile load mapping: each thread loads 2 float4 along K
    const int arow = t >> 2;          // 0..63
    const int acol = (t & 3) * 4;     // 0,4,8,12
    // B-tile NN mapping
    const int bkr = t >> 5;           // 0..7
    const int bnc = (t & 31) * 4;     // 0..124
    // B-tile NT mapping
    const int tbn = t >> 2;           // 0..63
    const int tbc = (t & 3) * 4;

    for (int k0 = 0; k0 < K; k0 += BK) {
#pragma unroll
        for (int i = 0; i < 2; i++) {
            int r = arow + i * 64;
            float4 v = *(const float4*)&A[(long long)(brow + r) * lda + k0 + acol];
            As[acol + 0][r] = v.x;
            As[acol + 1][r] = v.y;
            As[acol + 2][r] = v.z;
            As[acol + 3][r] = v.w;
        }
        if (!TB) {
#pragma unroll
            for (int i = 0; i < 2; i++) {
                int kk = bkr + i * 8;
                float4 v = *(const float4*)&B[(long long)(k0 + kk) * ldb + bcol + bnc];
                *(float4*)&Bs[kk][bnc] = v;
            }
        } else {
#pragma unroll
            for (int i = 0; i < 2; i++) {
                int n = tbn + i * 64;
                float4 v = *(const float4*)&B[(long long)(bcol + n) * ldb + k0 + tbc];
                Bs[tbc + 0][n] = v.x;
                Bs[tbc + 1][n] = v.y;
                Bs[tbc + 2][n] = v.z;
                Bs[tbc + 3][n] = v.w;
            }
        }
        __syncthreads();

#pragma unroll
        for (int kk = 0; kk < BK; kk++) {
            float a[8], b[8];
            *(float4*)&a[0] = *(const float4*)&As[kk][ty * 8];
            *(float4*)&a[4] = *(const float4*)&As[kk][ty * 8 + 4];
            *(float4*)&b[0] = *(const float4*)&Bs[kk][tx * 8];
            *(float4*)&b[4] = *(const float4*)&Bs[kk][tx * 8 + 4];
#pragma unroll
            for (int i = 0; i < 8; i++)
#pragma unroll
                for (int j = 0; j < 8; j++)
                    acc[i][j] += a[i] * b[j];
        }
        __syncthreads();
    }

    float bfr[8];
#pragma unroll
    for (int j = 0; j < 8; j++)
        bfr[j] = bias ? bias[bcol + tx * 8 + j] : 0.f;

#pragma unroll
    for (int i = 0; i < 8; i++) {
        long long r = brow + ty * 8 + i;
#pragma unroll
        for (int j = 0; j < 8; j += 4) {
            float4 v;
            v.x = alpha * acc[i][j + 0] + bfr[j + 0];
            v.y = alpha * acc[i][j + 1] + bfr[j + 1];
            v.z = alpha * acc[i][j + 2] + bfr[j + 2];
            v.w = alpha * acc[i][j + 3] + bfr[j + 3];
            *(float4*)&C[r * ldc + bcol + tx * 8 + j] = v;
        }
    }
}

// ---------------------------------------------------------------------------
// lambda scalar:  lam = exp(lq1.lk1) - exp(lq2.lk2) + (0.8 - 0.6*exp(0)) = ...+0.2
// ---------------------------------------------------------------------------
__global__ void lambda_kernel(const float* __restrict__ lq1, const float* __restrict__ lk1,
                              const float* __restrict__ lq2, const float* __restrict__ lk2)
{
    if (threadIdx.x == 0) {
        float d1 = 0.f, d2 = 0.f;
        for (int i = 0; i < 64; i++) {
            d1 += lq1[i] * lk1[i];
            d2 += lq2[i] * lk2[i];
        }
        g_lambda = expf(d1) - expf(d2) + (0.8f - 0.6f * expf(-0.3f * 0.0f));
    }
}

// cvec[n] = bo[n] + (1-lam) * sum_k bv[k]*Wo[k,n]
__global__ void cvec_kernel(const float* __restrict__ bv, const float* __restrict__ Wo,
                            const float* __restrict__ bo)
{
    int n = blockIdx.x * blockDim.x + threadIdx.x;
    if (n < 512) {
        float s = 0.f;
        for (int k = 0; k < 8192; k++) s += bv[k] * Wo[(long long)k * 512 + n];
        g_cvec[n] = bo[n] + (1.f - g_lambda) * s;
    }
}

// ---------------------------------------------------------------------------
// Fused dual softmax + differential combine:
//   out[row] = softmax(l1[row]) - lam * softmax(l2[row]), rows of length 2048
// One block (256 threads) per row; 8 elems/thread.
// ---------------------------------------------------------------------------
__global__ __launch_bounds__(256) void softmax_diff_kernel(
    const float* __restrict__ l1, const float* __restrict__ l2,
    float* __restrict__ out, int S)
{
    long long row = blockIdx.x;
    const float* r1 = l1 + row * S;
    const float* r2 = l2 + row * S;
    float* ro = out + row * S;
    const int t = threadIdx.x;
    const int lane = t & 31, warp = t >> 5;

    float v1[8], v2[8];
#pragma unroll
    for (int i = 0; i < 8; i++) {
        v1[i] = r1[t + i * 256];
        v2[i] = r2[t + i * 256];
    }

    float m1 = -1e30f, m2 = -1e30f;
#pragma unroll
    for (int i = 0; i < 8; i++) {
        m1 = fmaxf(m1, v1[i]);
        m2 = fmaxf(m2, v2[i]);
    }
#pragma unroll
    for (int o = 16; o; o >>= 1) {
        m1 = fmaxf(m1, __shfl_xor_sync(0xffffffffu, m1, o));
        m2 = fmaxf(m2, __shfl_xor_sync(0xffffffffu, m2, o));
    }
    __shared__ float s1[8], s2[8];
    if (lane == 0) { s1[warp] = m1; s2[warp] = m2; }
    __syncthreads();
    m1 = s1[0]; m2 = s2[0];
#pragma unroll
    for (int w = 1; w < 8; w++) {
        m1 = fmaxf(m1, s1[w]);
        m2 = fmaxf(m2, s2[w]);
    }

    float e1[8], e2[8];
    float sum1 = 0.f, sum2 = 0.f;
#pragma unroll
    for (int i = 0; i < 8; i++) {
        e1[i] = __expf(v1[i] - m1);
        e2[i] = __expf(v2[i] - m2);
        sum1 += e1[i];
        sum2 += e2[i];
    }
#pragma unroll
    for (int o = 16; o; o >>= 1) {
        sum1 += __shfl_xor_sync(0xffffffffu, sum1, o);
        sum2 += __shfl_xor_sync(0xffffffffu, sum2, o);
    }
    __syncthreads();
    if (lane == 0) { s1[warp] = sum1; s2[warp] = sum2; }
    __syncthreads();
    sum1 = 0.f; sum2 = 0.f;
#pragma unroll
    for (int w = 0; w < 8; w++) { sum1 += s1[w]; sum2 += s2[w]; }

    const float inv1 = 1.f / sum1;
    const float inv2 = g_lambda / sum2;
#pragma unroll
    for (int i = 0; i < 8; i++)
        ro[t + i * 256] = e1[i] * inv1 - e2[i] * inv2;
}

// ---------------------------------------------------------------------------
extern "C" void kernel_launch(void* const* d_in, const int* in_sizes, int n_in,
                              void* d_out, int out_size)
{
    const float* x    = (const float*)d_in[0];
    const float* Wqkv = (const float*)d_in[1];
    const float* bqkv = (const float*)d_in[2];
    const float* Wv   = (const float*)d_in[3];
    const float* bv   = (const float*)d_in[4];
    const float* Wo   = (const float*)d_in[5];
    const float* bo   = (const float*)d_in[6];
    const float* lq1  = (const float*)d_in[7];
    const float* lk1  = (const float*)d_in[8];
    const float* lq2  = (const float*)d_in[9];
    const float* lk2  = (const float*)d_in[10];
    float* out = (float*)d_out;

    float *qkv, *Mm, *Vp, *l1, *l2, *cvec;
    cudaGetSymbolAddress((void**)&qkv,  g_qkv);
    cudaGetSymbolAddress((void**)&Mm,   g_M);
    cudaGetSymbolAddress((void**)&Vp,   g_Vp);
    cudaGetSymbolAddress((void**)&l1,   g_l1);
    cudaGetSymbolAddress((void**)&l2,   g_l2);
    cudaGetSymbolAddress((void**)&cvec, g_cvec);

    const long long SQKV = 2048LL * 1024;   // per-batch stride in qkv
    const long long SLOG = 2048LL * 2048;   // per-batch stride in logits
    const long long SVP  = 2048LL * 512;    // per-batch stride in V'/out

    // 0) lambda scalar + folded bias vector
    lambda_kernel<<<1, 32>>>(lq1, lk1, lq2, lk2);
    cvec_kernel<<<2, 256>>>(bv, Wo, bo);

    // 1) qkv = x @ Wqkv + bqkv        [4096,1024], K=512
    sgemm_kernel<false><<<dim3(1024 / BN, 4096 / BM, 1), NTHREADS>>>(
        x, Wqkv, qkv, 4096, 1024, 512, 512, 1024, 1024, 0, 0, 0, 1.f, bqkv);

    // 2) M = Wv @ Wo                  [512,512], K=8192
    sgemm_kernel<false><<<dim3(512 / BN, 512 / BM, 1), NTHREADS>>>(
        Wv, Wo, Mm, 512, 512, 8192, 8192, 512, 512, 0, 0, 0, 1.f, nullptr);

    // 3) V' = x @ M                   [4096,512], K=512
    sgemm_kernel<false><<<dim3(512 / BN, 4096 / BM, 1), NTHREADS>>>(
        x, Mm, Vp, 4096, 512, 512, 512, 512, 512, 0, 0, 0, 1.f, nullptr);

    // 4) l1 = Q1 @ K1^T * 0.125 ;  l2 = Q2 @ K2^T * 0.125   (batched over z)
    sgemm_kernel<true><<<dim3(2048 / BN, 2048 / BM, 2), NTHREADS>>>(
        qkv + 0, qkv + 512, l1, 2048, 2048, 256, 1024, 1024, 2048,
        SQKV, SQKV, SLOG, 0.125f, nullptr);
    sgemm_kernel<true><<<dim3(2048 / BN, 2048 / BM, 2), NTHREADS>>>(
        qkv + 256, qkv + 768, l2, 2048, 2048, 256, 1024, 1024, 2048,
        SQKV, SQKV, SLOG, 0.125f, nullptr);

    // 5) diff = softmax(l1) - lam*softmax(l2)   (in place over l1)
    softmax_diff_kernel<<<4096, 256>>>(l1, l2, l1, 2048);

    // 6) out = diff @ V' + cvec       [2][2048,512], K=2048
    sgemm_kernel<false><<<dim3(512 / BN, 2048 / BM, 2), NTHREADS>>>(
        l1, Vp, out, 2048, 512, 2048, 2048, 512, 512,
        SLOG, SVP, SVP, 1.f, cvec);
}

// round 3
// speedup vs baseline: 1.7912x; 1.7912x over previous
#include <cuda_runtime.h>
#include <math.h>
#include <stdint.h>

// ---------------------------------------------------------------------------
// DifferentialAttention, algebraically folded, split-tf32 tensor-core GEMMs:
//   qkv  = x @ Wqkv + bqkv                       [4096,1024]
//   M    = Wv @ Wo                               [512,512]   (K=8192, splitK=16)
//   V'   = x @ M                                 [4096,512]
//   l1   = Q1 @ K1^T * 0.125 ; l2 = Q2 @ K2^T * 0.125      [2][2048,2048]
//   diff = softmax(l1) - lam*softmax(l2)         (in place over l1)
//   out  = diff @ V' + (1-lam)*(bv@Wo) + bo      [2][2048,512]  (splitK=2)
// Every GEMM runs tf32x2 (hi/lo split, 3 MMA passes) => ~fp32 accuracy.
// ---------------------------------------------------------------------------

#define BM 128
#define BN 128
#define BK 16
#define NTH 256
#define SST 136   // smem row stride in floats; 136 % 32 == 8 -> conflict-free frags

__device__ float g_qkv[4096 * 1024];
__device__ float g_M[512 * 512];
__device__ float g_Vp[4096 * 512];
__device__ float g_l1[2 * 2048 * 2048];
__device__ float g_l2[2 * 2048 * 2048];
__device__ float g_lambda;
__device__ float g_cvec[512];

__device__ __forceinline__ uint32_t f2tf(float x) {
    uint32_t r;
    asm("cvt.rna.tf32.f32 %0, %1;" : "=r"(r) : "f"(x));
    return r;
}

__device__ __forceinline__ void mma_tf32(float c[4],
                                         uint32_t a0, uint32_t a1, uint32_t a2, uint32_t a3,
                                         uint32_t b0, uint32_t b1) {
    asm volatile(
        "mma.sync.aligned.m16n8k8.row.col.f32.tf32.tf32.f32 "
        "{%0,%1,%2,%3}, {%4,%5,%6,%7}, {%8,%9}, {%0,%1,%2,%3};"
        : "+f"(c[0]), "+f"(c[1]), "+f"(c[2]), "+f"(c[3])
        : "r"(a0), "r"(a1), "r"(a2), "r"(a3), "r"(b0), "r"(b1));
}

// ---------------------------------------------------------------------------
// Split-tf32 GEMM. C = alpha*A@B(^T) (+bias). grid.z = batch * splitk.
// splitk>1 path uses atomicAdd into pre-zeroed C; bias added by chunk 0.
// Assumes M%128==0, N%128==0, K%(16*splitk)==0.
// ---------------------------------------------------------------------------
template <bool TB>
__global__ __launch_bounds__(NTH, 1) void mma_gemm(
    const float* __restrict__ A, const float* __restrict__ B,
    float* __restrict__ C,
    int Mdim, int Ndim, int K, int lda, int ldb, int ldc,
    long long sA, long long sB, long long sC,
    float alpha, const float* __restrict__ bias, int splitk)
{
    const int zb = blockIdx.z / splitk;
    const int kchunk = blockIdx.z % splitk;
    const int kc = K / splitk;
    const int kbeg = kchunk * kc;
    const int kend = kbeg + kc;

    A += (long long)zb * sA;
    B += (long long)zb * sB;
    C += (long long)zb * sC;

    const int brow = blockIdx.y * BM;
    const int bcol = blockIdx.x * BN;
    const int t = threadIdx.x;
    const int lane = t & 31;
    const int wid = t >> 5;
    const int wm = (wid >> 2) * 64;   // warp row offset (2 warps in m)
    const int wn = (wid & 3) * 32;    // warp col offset (4 warps in n)
    const int q = lane & 3;           // threadID_in_group
    const int r = lane >> 2;          // groupID

    __shared__ float As[2 * BK * SST];   // [hi/lo][k][m]
    __shared__ float Bs[2 * BK * SST];   // [hi/lo][k][n]

    float acc[4][4][4];
#pragma unroll
    for (int i = 0; i < 4; i++)
#pragma unroll
        for (int j = 0; j < 4; j++)
#pragma unroll
            for (int c = 0; c < 4; c++) acc[i][j][c] = 0.f;

    // gmem load mappings
    const int akq = (t & 3) * 4;   // k offset for A (and TB-B) float4
    const int am  = t >> 2;        // row 0..63 (+64)
    const int bnc = (t & 31) * 4;  // n offset for NN-B float4
    const int bkr = t >> 5;        // k row 0..7 (+8) for NN-B

    float4 abuf0, abuf1, bbuf0, bbuf1;

    // prologue gmem load
    abuf0 = *(const float4*)&A[(long long)(brow + am) * lda + kbeg + akq];
    abuf1 = *(const float4*)&A[(long long)(brow + am + 64) * lda + kbeg + akq];
    if (!TB) {
        bbuf0 = *(const float4*)&B[(long long)(kbeg + bkr) * ldb + bcol + bnc];
        bbuf1 = *(const float4*)&B[(long long)(kbeg + bkr + 8) * ldb + bcol + bnc];
    } else {
        bbuf0 = *(const float4*)&B[(long long)(bcol + am) * ldb + kbeg + akq];
        bbuf1 = *(const float4*)&B[(long long)(bcol + am + 64) * ldb + kbeg + akq];
    }

    for (int k0 = kbeg; k0 < kend; k0 += BK) {
        // split + store staged regs into smem
        {
            float va[8] = {abuf0.x, abuf0.y, abuf0.z, abuf0.w,
                           abuf1.x, abuf1.y, abuf1.z, abuf1.w};
#pragma unroll
            for (int h = 0; h < 2; h++) {
                int mrow = am + h * 64;
#pragma unroll
                for (int j = 0; j < 4; j++) {
                    float x = va[h * 4 + j];
                    float hf = __uint_as_float(f2tf(x));
                    float lf = __uint_as_float(f2tf(x - hf));
                    As[(akq + j) * SST + mrow] = hf;
                    As[BK * SST + (akq + j) * SST + mrow] = lf;
                }
            }
            float vb[8] = {bbuf0.x, bbuf0.y, bbuf0.z, bbuf0.w,
                           bbuf1.x, bbuf1.y, bbuf1.z, bbuf1.w};
            if (!TB) {
#pragma unroll
                for (int h = 0; h < 2; h++) {
                    int krow = bkr + h * 8;
                    float4 hv, lv;
                    float hx;
                    hx = __uint_as_float(f2tf(vb[h*4+0])); hv.x = hx; lv.x = __uint_as_float(f2tf(vb[h*4+0]-hx));
                    hx = __uint_as_float(f2tf(vb[h*4+1])); hv.y = hx; lv.y = __uint_as_float(f2tf(vb[h*4+1]-hx));
                    hx = __uint_as_float(f2tf(vb[h*4+2])); hv.z = hx; lv.z = __uint_as_float(f2tf(vb[h*4+2]-hx));
                    hx = __uint_as_float(f2tf(vb[h*4+3])); hv.w = hx; lv.w = __uint_as_float(f2tf(vb[h*4+3]-hx));
                    *(float4*)&Bs[krow * SST + bnc] = hv;
                    *(float4*)&Bs[BK * SST + krow * SST + bnc] = lv;
                }
            } else {
#pragma unroll
                for (int h = 0; h < 2; h++) {
                    int nrow = am + h * 64;
#pragma unroll
                    for (int j = 0; j < 4; j++) {
                        float x = vb[h * 4 + j];
                        float hf = __uint_as_float(f2tf(x));
                        float lf = __uint_as_float(f2tf(x - hf));
                        Bs[(akq + j) * SST + nrow] = hf;
                        Bs[BK * SST + (akq + j) * SST + nrow] = lf;
                    }
                }
            }
        }
        __syncthreads();

        // prefetch next tile into regs (overlaps with compute below)
        if (k0 + BK < kend) {
            int kn = k0 + BK;
            abuf0 = *(const float4*)&A[(long long)(brow + am) * lda + kn + akq];
            abuf1 = *(const float4*)&A[(long long)(brow + am + 64) * lda + kn + akq];
            if (!TB) {
                bbuf0 = *(const float4*)&B[(long long)(kn + bkr) * ldb + bcol + bnc];
                bbuf1 = *(const float4*)&B[(long long)(kn + bkr + 8) * ldb + bcol + bnc];
            } else {
                bbuf0 = *(const float4*)&B[(long long)(bcol + am) * ldb + kn + akq];
                bbuf1 = *(const float4*)&B[(long long)(bcol + am + 64) * ldb + kn + akq];
            }
        }

        // compute: 2 k-steps of 8, 3 split passes each
#pragma unroll
        for (int ks = 0; ks < 2; ks++) {
            const int kb = ks * 8 + q;
            uint32_t Bh[4][2], Bl[4][2];
#pragma unroll
            for (int nt = 0; nt < 4; nt++) {
                int n = wn + nt * 8 + r;
                Bh[nt][0] = __float_as_uint(Bs[kb * SST + n]);
                Bh[nt][1] = __float_as_uint(Bs[(kb + 4) * SST + n]);
                Bl[nt][0] = __float_as_uint(Bs[BK * SST + kb * SST + n]);
                Bl[nt][1] = __float_as_uint(Bs[BK * SST + (kb + 4) * SST + n]);
            }
#pragma unroll
            for (int mt = 0; mt < 4; mt++) {
                int m = wm + mt * 16 + r;
                uint32_t Ah0 = __float_as_uint(As[kb * SST + m]);
                uint32_t Ah1 = __float_as_uint(As[kb * SST + m + 8]);
                uint32_t Ah2 = __float_as_uint(As[(kb + 4) * SST + m]);
                uint32_t Ah3 = __float_as_uint(As[(kb + 4) * SST + m + 8]);
                uint32_t Al0 = __float_as_uint(As[BK * SST + kb * SST + m]);
                uint32_t Al1 = __float_as_uint(As[BK * SST + kb * SST + m + 8]);
                uint32_t Al2 = __float_as_uint(As[BK * SST + (kb + 4) * SST + m]);
                uint32_t Al3 = __float_as_uint(As[BK * SST + (kb + 4) * SST + m + 8]);
#pragma unroll
                for (int nt = 0; nt < 4; nt++) {
                    mma_tf32(acc[mt][nt], Ah0, Ah1, Ah2, Ah3, Bh[nt][0], Bh[nt][1]);
                    mma_tf32(acc[mt][nt], Ah0, Ah1, Ah2, Ah3, Bl[nt][0], Bl[nt][1]);
                    mma_tf32(acc[mt][nt], Al0, Al1, Al2, Al3, Bh[nt][0], Bh[nt][1]);
                }
            }
        }
        __syncthreads();
    }

    // epilogue
#pragma unroll
    for (int mt = 0; mt < 4; mt++) {
#pragma unroll
        for (int nt = 0; nt < 4; nt++) {
            int row = brow + wm + mt * 16 + r;
            int col = bcol + wn + nt * 8 + 2 * q;
            float b0 = 0.f, b1 = 0.f;
            if (bias && kchunk == 0) { b0 = bias[col]; b1 = bias[col + 1]; }
            float v0 = alpha * acc[mt][nt][0] + b0;
            float v1 = alpha * acc[mt][nt][1] + b1;
            float v2 = alpha * acc[mt][nt][2] + b0;
            float v3 = alpha * acc[mt][nt][3] + b1;
            if (splitk > 1) {
                atomicAdd(&C[(long long)row * ldc + col], v0);
                atomicAdd(&C[(long long)row * ldc + col + 1], v1);
                atomicAdd(&C[(long long)(row + 8) * ldc + col], v2);
                atomicAdd(&C[(long long)(row + 8) * ldc + col + 1], v3);
            } else {
                float2 p0 = make_float2(v0, v1);
                float2 p1 = make_float2(v2, v3);
                *(float2*)&C[(long long)row * ldc + col] = p0;
                *(float2*)&C[(long long)(row + 8) * ldc + col] = p1;
            }
        }
    }
}

// ---------------------------------------------------------------------------
__global__ void lambda_kernel(const float* __restrict__ lq1, const float* __restrict__ lk1,
                              const float* __restrict__ lq2, const float* __restrict__ lk2)
{
    if (threadIdx.x == 0) {
        float d1 = 0.f, d2 = 0.f;
        for (int i = 0; i < 64; i++) {
            d1 += lq1[i] * lk1[i];
            d2 += lq2[i] * lk2[i];
        }
        g_lambda = expf(d1) - expf(d2) + (0.8f - 0.6f * expf(-0.3f * 0.0f));
    }
}

// cvec[n] = bo[n] + (1-lam) * sum_k bv[k]*Wo[k,n]
__global__ void cvec_kernel(const float* __restrict__ bv, const float* __restrict__ Wo,
                            const float* __restrict__ bo)
{
    int n = blockIdx.x * blockDim.x + threadIdx.x;
    if (n < 512) {
        float s = 0.f;
        for (int k = 0; k < 8192; k++) s += bv[k] * Wo[(long long)k * 512 + n];
        g_cvec[n] = bo[n] + (1.f - g_lambda) * s;
    }
}

// ---------------------------------------------------------------------------
// Fused dual softmax + differential combine (rows of length 2048).
// ---------------------------------------------------------------------------
__global__ __launch_bounds__(256) void softmax_diff_kernel(
    const float* __restrict__ l1, const float* __restrict__ l2,
    float* __restrict__ out, int S)
{
    long long row = blockIdx.x;
    const float* r1 = l1 + row * S;
    const float* r2 = l2 + row * S;
    float* ro = out + row * S;
    const int t = threadIdx.x;
    const int lane = t & 31, warp = t >> 5;

    float v1[8], v2[8];
#pragma unroll
    for (int i = 0; i < 8; i++) {
        v1[i] = r1[t + i * 256];
        v2[i] = r2[t + i * 256];
    }

    float m1 = -1e30f, m2 = -1e30f;
#pragma unroll
    for (int i = 0; i < 8; i++) {
        m1 = fmaxf(m1, v1[i]);
        m2 = fmaxf(m2, v2[i]);
    }
#pragma unroll
    for (int o = 16; o; o >>= 1) {
        m1 = fmaxf(m1, __shfl_xor_sync(0xffffffffu, m1, o));
        m2 = fmaxf(m2, __shfl_xor_sync(0xffffffffu, m2, o));
    }
    __shared__ float s1[8], s2[8];
    if (lane == 0) { s1[warp] = m1; s2[warp] = m2; }
    __syncthreads();
    m1 = s1[0]; m2 = s2[0];
#pragma unroll
    for (int w = 1; w < 8; w++) {
        m1 = fmaxf(m1, s1[w]);
        m2 = fmaxf(m2, s2[w]);
    }

    float e1[8], e2[8];
    float sum1 = 0.f, sum2 = 0.f;
#pragma unroll
    for (int i = 0; i < 8; i++) {
        e1[i] = __expf(v1[i] - m1);
        e2[i] = __expf(v2[i] - m2);
        sum1 += e1[i];
        sum2 += e2[i];
    }
#pragma unroll
    for (int o = 16; o; o >>= 1) {
        sum1 += __shfl_xor_sync(0xffffffffu, sum1, o);
        sum2 += __shfl_xor_sync(0xffffffffu, sum2, o);
    }
    __syncthreads();
    if (lane == 0) { s1[warp] = sum1; s2[warp] = sum2; }
    __syncthreads();
    sum1 = 0.f; sum2 = 0.f;
#pragma unroll
    for (int w = 0; w < 8; w++) { sum1 += s1[w]; sum2 += s2[w]; }

    const float inv1 = 1.f / sum1;
    const float inv2 = g_lambda / sum2;
#pragma unroll
    for (int i = 0; i < 8; i++)
        ro[t + i * 256] = e1[i] * inv1 - e2[i] * inv2;
}

// ---------------------------------------------------------------------------
extern "C" void kernel_launch(void* const* d_in, const int* in_sizes, int n_in,
                              void* d_out, int out_size)
{
    const float* x    = (const float*)d_in[0];
    const float* Wqkv = (const float*)d_in[1];
    const float* bqkv = (const float*)d_in[2];
    const float* Wv   = (const float*)d_in[3];
    const float* bv   = (const float*)d_in[4];
    const float* Wo   = (const float*)d_in[5];
    const float* bo   = (const float*)d_in[6];
    const float* lq1  = (const float*)d_in[7];
    const float* lk1  = (const float*)d_in[8];
    const float* lq2  = (const float*)d_in[9];
    const float* lk2  = (const float*)d_in[10];
    float* out = (float*)d_out;

    float *qkv, *Mm, *Vp, *l1, *l2, *cvec;
    cudaGetSymbolAddress((void**)&qkv,  g_qkv);
    cudaGetSymbolAddress((void**)&Mm,   g_M);
    cudaGetSymbolAddress((void**)&Vp,   g_Vp);
    cudaGetSymbolAddress((void**)&l1,   g_l1);
    cudaGetSymbolAddress((void**)&l2,   g_l2);
    cudaGetSymbolAddress((void**)&cvec, g_cvec);

    const long long SQKV = 2048LL * 1024;
    const long long SLOG = 2048LL * 2048;
    const long long SVP  = 2048LL * 512;

    // 0) lambda scalar + folded bias vector
    lambda_kernel<<<1, 32>>>(lq1, lk1, lq2, lk2);
    cvec_kernel<<<2, 256>>>(bv, Wo, bo);

    // 1) qkv = x @ Wqkv + bqkv        [4096,1024], K=512
    mma_gemm<false><<<dim3(1024 / BN, 4096 / BM, 1), NTH>>>(
        x, Wqkv, qkv, 4096, 1024, 512, 512, 1024, 1024, 0, 0, 0, 1.f, bqkv, 1);

    // 2) M = Wv @ Wo                  [512,512], K=8192, splitK=16
    cudaMemsetAsync(Mm, 0, 512 * 512 * sizeof(float));
    mma_gemm<false><<<dim3(512 / BN, 512 / BM, 16), NTH>>>(
        Wv, Wo, Mm, 512, 512, 8192, 8192, 512, 512, 0, 0, 0, 1.f, nullptr, 16);

    // 3) V' = x @ M                   [4096,512], K=512
    mma_gemm<false><<<dim3(512 / BN, 4096 / BM, 1), NTH>>>(
        x, Mm, Vp, 4096, 512, 512, 512, 512, 512, 0, 0, 0, 1.f, nullptr, 1);

    // 4) logits (batched over z)
    mma_gemm<true><<<dim3(2048 / BN, 2048 / BM, 2), NTH>>>(
        qkv + 0, qkv + 512, l1, 2048, 2048, 256, 1024, 1024, 2048,
        SQKV, SQKV, SLOG, 0.125f, nullptr, 1);
    mma_gemm<true><<<dim3(2048 / BN, 2048 / BM, 2), NTH>>>(
        qkv + 256, qkv + 768, l2, 2048, 2048, 256, 1024, 1024, 2048,
        SQKV, SQKV, SLOG, 0.125f, nullptr, 1);

    // 5) diff = softmax(l1) - lam*softmax(l2)   (in place over l1)
    softmax_diff_kernel<<<4096, 256>>>(l1, l2, l1, 2048);

    // 6) out = diff @ V' + cvec       [2][2048,512], K=2048, splitK=2
    cudaMemsetAsync(out, 0, 2 * 2048 * 512 * sizeof(float));
    mma_gemm<false><<<dim3(512 / BN, 2048 / BM, 4), NTH>>>(
        l1, Vp, out, 2048, 512, 2048, 2048, 512, 512,
        SLOG, SVP, SVP, 1.f, cvec, 2);
}

// round 5
// speedup vs baseline: 2.0327x; 1.1348x over previous
#include <cuda_runtime.h>
#include <math.h>
#include <stdint.h>

// ---------------------------------------------------------------------------
// DifferentialAttention, algebraically folded, split-tf32 tensor-core GEMMs,
// cp.async double-buffered pipeline, split-at-consume:
//   qkv  = x @ Wqkv + bqkv                       [4096,1024]
//   M    = Wv @ Wo                               [512,512]   (K=8192, splitK=16)
//   V'   = x @ M                                 [4096,512]  (splitK=2)
//   l1   = Q1 @ K1^T * 0.125 ; l2 = Q2 @ K2^T * 0.125   (merged z=4 launch)
//   diff = softmax(l1) - lam*softmax(l2)         (in place over l1)
//   out  = diff @ V' + (1-lam)*(bv@Wo) + bo      [2][2048,512]  (splitK=2)
// ---------------------------------------------------------------------------

#define BM 128
#define BN 128
#define BK 16
#define NTH 256
#define SSA 20     // [row][k] stride (A and TB-B): banks r*20+q all distinct
#define SSB 136    // [k][n]   stride (NN-B): banks 8q+r all distinct

__device__ float g_qkv[4096 * 1024];
__device__ float g_M[512 * 512];
__device__ float g_Vp[4096 * 512];
__device__ float g_l1[2 * 2048 * 2048];
__device__ float g_l2[2 * 2048 * 2048];
__device__ float g_lambda;
__device__ float g_cvec[512];

__device__ __forceinline__ float f2tf(float x) {
    uint32_t r;
    asm("cvt.rna.tf32.f32 %0, %1;" : "=r"(r) : "f"(x));
    return __uint_as_float(r);
}

__device__ __forceinline__ void mma_tf32(float c[4],
                                         uint32_t a0, uint32_t a1, uint32_t a2, uint32_t a3,
                                         uint32_t b0, uint32_t b1) {
    asm volatile(
        "mma.sync.aligned.m16n8k8.row.col.f32.tf32.tf32.f32 "
        "{%0,%1,%2,%3}, {%4,%5,%6,%7}, {%8,%9}, {%0,%1,%2,%3};"
        : "+f"(c[0]), "+f"(c[1]), "+f"(c[2]), "+f"(c[3])
        : "r"(a0), "r"(a1), "r"(a2), "r"(a3), "r"(b0), "r"(b1));
}

__device__ __forceinline__ void cpa16(uint32_t smem, const void* gmem) {
    asm volatile("cp.async.ca.shared.global [%0], [%1], 16;" :: "r"(smem), "l"(gmem));
}
__device__ __forceinline__ void cpa_commit() {
    asm volatile("cp.async.commit_group;");
}
template <int N>
__device__ __forceinline__ void cpa_wait() {
    asm volatile("cp.async.wait_group %0;" :: "n"(N));
}

// ---------------------------------------------------------------------------
// Split-tf32 GEMM, 2-stage cp.async pipeline. C = alpha*A@B(^T) (+bias).
// grid.z = batch*splitk. splitk>1: atomicAdd into zeroed C, bias by chunk 0.
// Calt: logits merge — z in [0,2) -> C batch z; z in [2,4) -> Calt, A/B +selOff.
// ---------------------------------------------------------------------------
template <bool TB>
__global__ __launch_bounds__(NTH, 1) void mma_gemm(
    const float* __restrict__ A, const float* __restrict__ B,
    float* __restrict__ C, float* __restrict__ Calt,
    int K, int lda, int ldb, int ldc,
    long long sA, long long sB, long long sC,
    float alpha, const float* __restrict__ bias, int splitk, int selOff)
{
    int zb = blockIdx.z / splitk;
    const int kchunk = blockIdx.z % splitk;
    if (Calt) {
        int sel = zb >> 1;
        zb &= 1;
        if (sel) { A += selOff; B += selOff; C = Calt; }
    }
    const int kc = K / splitk;
    const int kbeg = kchunk * kc;

    A += (long long)zb * sA;
    B += (long long)zb * sB;
    C += (long long)zb * sC;

    const int brow = blockIdx.y * BM;
    const int bcol = blockIdx.x * BN;
    const int t = threadIdx.x;
    const int lane = t & 31;
    const int wid = t >> 5;
    const int wm = (wid >> 2) * 64;
    const int wn = (wid & 3) * 32;
    const int q = lane & 3;
    const int r = lane >> 2;

    __shared__ __align__(16) float As[2][BM * SSA];             // raw fp32 [m][k]
    __shared__ __align__(16) float Bs[2][BM * SSA];             // TB:[n][k] / NN:[k][n]

    const uint32_t sa_base = (uint32_t)__cvta_generic_to_shared(&As[0][0]);
    const uint32_t sb_base = (uint32_t)__cvta_generic_to_shared(&Bs[0][0]);

    float acc[4][4][4];
#pragma unroll
    for (int i = 0; i < 4; i++)
#pragma unroll
        for (int j = 0; j < 4; j++)
#pragma unroll
            for (int c = 0; c < 4; c++) acc[i][j][c] = 0.f;

    // cp.async chunk mappings (512 chunks of 16B per tile, 2 per thread)
    const int am  = t >> 2;          // A/TB-B row 0..63 (+64)
    const int akq = (t & 3) * 4;     // k offset
    const int bkr = t >> 5;          // NN-B k row 0..7 (+8)
    const int bnc = (t & 31) * 4;    // NN-B n offset

    auto load_stage = [&](int st, int k0) {
        uint32_t sa = sa_base + (uint32_t)(st * BM * SSA * 4);
        uint32_t sb = sb_base + (uint32_t)(st * BM * SSA * 4);
#pragma unroll
        for (int i = 0; i < 2; i++) {
            int m = am + i * 64;
            cpa16(sa + (uint32_t)((m * SSA + akq) * 4),
                  &A[(long long)(brow + m) * lda + k0 + akq]);
        }
        if (!TB) {
#pragma unroll
            for (int i = 0; i < 2; i++) {
                int kk = bkr + i * 8;
                cpa16(sb + (uint32_t)((kk * SSB + bnc) * 4),
                      &B[(long long)(k0 + kk) * ldb + bcol + bnc]);
            }
        } else {
#pragma unroll
            for (int i = 0; i < 2; i++) {
                int n = am + i * 64;
                cpa16(sb + (uint32_t)((n * SSA + akq) * 4),
                      &B[(long long)(bcol + n) * ldb + k0 + akq]);
            }
        }
        cpa_commit();
    };

    const int nIter = kc / BK;
    load_stage(0, kbeg);

    for (int it = 0; it < nIter; it++) {
        if (it + 1 < nIter) {
            load_stage((it + 1) & 1, kbeg + (it + 1) * BK);
            cpa_wait<1>();
        } else {
            cpa_wait<0>();
        }
        __syncthreads();

        const float* As_ = As[it & 1];
        const float* Bs_ = Bs[it & 1];

#pragma unroll
        for (int ks = 0; ks < 2; ks++) {
            const int kb = ks * 8 + q;
            uint32_t Bh[4][2], Bl[4][2];
#pragma unroll
            for (int nt = 0; nt < 4; nt++) {
                int n = wn + nt * 8 + r;
                float b0 = TB ? Bs_[n * SSA + kb]     : Bs_[kb * SSB + n];
                float b1 = TB ? Bs_[n * SSA + kb + 4] : Bs_[(kb + 4) * SSB + n];
                float h0 = f2tf(b0), h1 = f2tf(b1);
                Bh[nt][0] = __float_as_uint(h0);
                Bh[nt][1] = __float_as_uint(h1);
                Bl[nt][0] = __float_as_uint(b0 - h0);
                Bl[nt][1] = __float_as_uint(b1 - h1);
            }
#pragma unroll
            for (int mt = 0; mt < 4; mt++) {
                int m = wm + mt * 16 + r;
                float a0 = As_[m * SSA + kb];
                float a1 = As_[(m + 8) * SSA + kb];
                float a2 = As_[m * SSA + kb + 4];
                float a3 = As_[(m + 8) * SSA + kb + 4];
                float h0 = f2tf(a0), h1 = f2tf(a1), h2 = f2tf(a2), h3 = f2tf(a3);
                uint32_t Ah0 = __float_as_uint(h0), Ah1 = __float_as_uint(h1);
                uint32_t Ah2 = __float_as_uint(h2), Ah3 = __float_as_uint(h3);
                uint32_t Al0 = __float_as_uint(a0 - h0), Al1 = __float_as_uint(a1 - h1);
                uint32_t Al2 = __float_as_uint(a2 - h2), Al3 = __float_as_uint(a3 - h3);
#pragma unroll
                for (int nt = 0; nt < 4; nt++) {
                    mma_tf32(acc[mt][nt], Ah0, Ah1, Ah2, Ah3, Bh[nt][0], Bh[nt][1]);
                    mma_tf32(acc[mt][nt], Ah0, Ah1, Ah2, Ah3, Bl[nt][0], Bl[nt][1]);
                    mma_tf32(acc[mt][nt], Al0, Al1, Al2, Al3, Bh[nt][0], Bh[nt][1]);
                }
            }
        }
        __syncthreads();
    }

    // epilogue
#pragma unroll
    for (int mt = 0; mt < 4; mt++) {
#pragma unroll
        for (int nt = 0; nt < 4; nt++) {
            int row = brow + wm + mt * 16 + r;
            int col = bcol + wn + nt * 8 + 2 * q;
            float b0 = 0.f, b1 = 0.f;
            if (bias && kchunk == 0) { b0 = bias[col]; b1 = bias[col + 1]; }
            float v0 = alpha * acc[mt][nt][0] + b0;
            float v1 = alpha * acc[mt][nt][1] + b1;
            float v2 = alpha * acc[mt][nt][2] + b0;
            float v3 = alpha * acc[mt][nt][3] + b1;
            if (splitk > 1) {
                atomicAdd(&C[(long long)row * ldc + col], v0);
                atomicAdd(&C[(long long)row * ldc + col + 1], v1);
                atomicAdd(&C[(long long)(row + 8) * ldc + col], v2);
                atomicAdd(&C[(long long)(row + 8) * ldc + col + 1], v3);
            } else {
                *(float2*)&C[(long long)row * ldc + col] = make_float2(v0, v1);
                *(float2*)&C[(long long)(row + 8) * ldc + col] = make_float2(v2, v3);
            }
        }
    }
}

// ---------------------------------------------------------------------------
__global__ void lambda_kernel(const float* __restrict__ lq1, const float* __restrict__ lk1,
                              const float* __restrict__ lq2, const float* __restrict__ lk2)
{
    if (threadIdx.x == 0) {
        float d1 = 0.f, d2 = 0.f;
        for (int i = 0; i < 64; i++) {
            d1 += lq1[i] * lk1[i];
            d2 += lq2[i] * lk2[i];
        }
        g_lambda = expf(d1) - expf(d2) + (0.8f - 0.6f * expf(-0.3f * 0.0f));
    }
}

// cvec[n] = bo[n] + (1-lam) * sum_k bv[k]*Wo[k,n]
__global__ void cvec_kernel(const float* __restrict__ bv, const float* __restrict__ Wo,
                            const float* __restrict__ bo)
{
    int n = blockIdx.x * blockDim.x + threadIdx.x;
    if (n < 512) {
        float s = 0.f;
        for (int k = 0; k < 8192; k++) s += bv[k] * Wo[(long long)k * 512 + n];
        g_cvec[n] = bo[n] + (1.f - g_lambda) * s;
    }
}

// ---------------------------------------------------------------------------
// Fused dual softmax + differential combine (rows of length 2048).
// ---------------------------------------------------------------------------
__global__ __launch_bounds__(256) void softmax_diff_kernel(
    const float* __restrict__ l1, const float* __restrict__ l2,
    float* __restrict__ out, int S)
{
    long long row = blockIdx.x;
    const float* r1 = l1 + row * S;
    const float* r2 = l2 + row * S;
    float* ro = out + row * S;
    const int t = threadIdx.x;
    const int lane = t & 31, warp = t >> 5;

    float v1[8], v2[8];
#pragma unroll
    for (int i = 0; i < 8; i++) {
        v1[i] = r1[t + i * 256];
        v2[i] = r2[t + i * 256];
    }

    float m1 = -1e30f, m2 = -1e30f;
#pragma unroll
    for (int i = 0; i < 8; i++) {
        m1 = fmaxf(m1, v1[i]);
        m2 = fmaxf(m2, v2[i]);
    }
#pragma unroll
    for (int o = 16; o; o >>= 1) {
        m1 = fmaxf(m1, __shfl_xor_sync(0xffffffffu, m1, o));
        m2 = fmaxf(m2, __shfl_xor_sync(0xffffffffu, m2, o));
    }
    __shared__ float s1[8], s2[8];
    if (lane == 0) { s1[warp] = m1; s2[warp] = m2; }
    __syncthreads();
    m1 = s1[0]; m2 = s2[0];
#pragma unroll
    for (int w = 1; w < 8; w++) {
        m1 = fmaxf(m1, s1[w]);
        m2 = fmaxf(m2, s2[w]);
    }

    float e1[8], e2[8];
    float sum1 = 0.f, sum2 = 0.f;
#pragma unroll
    for (int i = 0; i < 8; i++) {
        e1[i] = __expf(v1[i] - m1);
        e2[i] = __expf(v2[i] - m2);
        sum1 += e1[i];
        sum2 += e2[i];
    }
#pragma unroll
    for (int o = 16; o; o >>= 1) {
        sum1 += __shfl_xor_sync(0xffffffffu, sum1, o);
        sum2 += __shfl_xor_sync(0xffffffffu, sum2, o);
    }
    __syncthreads();
    if (lane == 0) { s1[warp] = sum1; s2[warp] = sum2; }
    __syncthreads();
    sum1 = 0.f; sum2 = 0.f;
#pragma unroll
    for (int w = 0; w < 8; w++) { sum1 += s1[w]; sum2 += s2[w]; }

    const float inv1 = 1.f / sum1;
    const float inv2 = g_lambda / sum2;
#pragma unroll
    for (int i = 0; i < 8; i++)
        ro[t + i * 256] = e1[i] * inv1 - e2[i] * inv2;
}

// ---------------------------------------------------------------------------
extern "C" void kernel_launch(void* const* d_in, const int* in_sizes, int n_in,
                              void* d_out, int out_size)
{
    const float* x    = (const float*)d_in[0];
    const float* Wqkv = (const float*)d_in[1];
    const float* bqkv = (const float*)d_in[2];
    const float* Wv   = (const float*)d_in[3];
    const float* bv   = (const float*)d_in[4];
    const float* Wo   = (const float*)d_in[5];
    const float* bo   = (const float*)d_in[6];
    const float* lq1  = (const float*)d_in[7];
    const float* lk1  = (const float*)d_in[8];
    const float* lq2  = (const float*)d_in[9];
    const float* lk2  = (const float*)d_in[10];
    float* out = (float*)d_out;

    float *qkv, *Mm, *Vp, *l1, *l2, *cvec;
    cudaGetSymbolAddress((void**)&qkv,  g_qkv);
    cudaGetSymbolAddress((void**)&Mm,   g_M);
    cudaGetSymbolAddress((void**)&Vp,   g_Vp);
    cudaGetSymbolAddress((void**)&l1,   g_l1);
    cudaGetSymbolAddress((void**)&l2,   g_l2);
    cudaGetSymbolAddress((void**)&cvec, g_cvec);

    const long long SQKV = 2048LL * 1024;
    const long long SLOG = 2048LL * 2048;
    const long long SVP  = 2048LL * 512;

    // 0) lambda scalar + folded bias vector
    lambda_kernel<<<1, 32>>>(lq1, lk1, lq2, lk2);
    cvec_kernel<<<2, 256>>>(bv, Wo, bo);

    // 1) qkv = x @ Wqkv + bqkv        [4096,1024], K=512
    mma_gemm<false><<<dim3(1024 / BN, 4096 / BM, 1), NTH>>>(
        x, Wqkv, qkv, nullptr, 512, 512, 1024, 1024, 0, 0, 0, 1.f, bqkv, 1, 0);

    // 2) M = Wv @ Wo                  [512,512], K=8192, splitK=16
    cudaMemsetAsync(Mm, 0, 512 * 512 * sizeof(float));
    mma_gemm<false><<<dim3(512 / BN, 512 / BM, 16), NTH>>>(
        Wv, Wo, Mm, nullptr, 8192, 8192, 512, 512, 0, 0, 0, 1.f, nullptr, 16, 0);

    // 3) V' = x @ M                   [4096,512], K=512, splitK=2
    cudaMemsetAsync(Vp, 0, 4096 * 512 * sizeof(float));
    mma_gemm<false><<<dim3(512 / BN, 4096 / BM, 2), NTH>>>(
        x, Mm, Vp, nullptr, 512, 512, 512, 512, 0, 0, 0, 1.f, nullptr, 2, 0);

    // 4) logits merged: z=0,1 -> l1 (Q1/K1); z=2,3 -> l2 (Q2/K2, offset +256)
    mma_gemm<true><<<dim3(2048 / BN, 2048 / BM, 4), NTH>>>(
        qkv + 0, qkv + 512, l1, l2, 256, 1024, 1024, 2048,
        SQKV, SQKV, SLOG, 0.125f, nullptr, 1, 256);

    // 5) diff = softmax(l1) - lam*softmax(l2)   (in place over l1)
    softmax_diff_kernel<<<4096, 256>>>(l1, l2, l1, 2048);

    // 6) out = diff @ V' + cvec       [2][2048,512], K=2048, splitK=2
    cudaMemsetAsync(out, 0, 2 * 2048 * 512 * sizeof(float));
    mma_gemm<false><<<dim3(512 / BN, 2048 / BM, 4), NTH>>>(
        l1, Vp, out, nullptr, 2048, 2048, 512, 512,
        SLOG, SVP, SVP, 1.f, cvec, 2, 0);
}

// round 6
// speedup vs baseline: 2.2677x; 1.1156x over previous
#include <cuda_runtime.h>
#include <math.h>
#include <stdint.h>

// ---------------------------------------------------------------------------
// DifferentialAttention, algebraically folded, bf16x2 (3-pass) tensor-core
// GEMMs with cp.async double-buffered pipeline, split-at-consume:
//   qkv  = x @ Wqkv + bqkv                       [4096,1024]
//   M    = Wv @ Wo                               [512,512]   (K=8192, splitK=16)
//   V'   = x @ M                                 [4096,512]  (splitK=2)
//   l1   = Q1 @ K1^T * 0.125 ; l2 = Q2 @ K2^T * 0.125   (merged z=4 launch)
//   diff = softmax(l1) - lam*softmax(l2)         (in place over l1)
//   out  = diff @ V' + (1-lam)*(bv@Wo) + bo      [2][2048,512]  (splitK=2)
// Each fp32 element splits to bf16 hi+lo; 3 MMA passes (hh, hl, lh) give
// ~2^-18 per-element error => final rel_err ~1e-5, at 2x tf32 tensor rate.
// ---------------------------------------------------------------------------

#define BM 128
#define BN 128
#define BK 16
#define NTH 256
#define SSA 24     // [row][k] stride (A, TB-B): LDS.64 banks 8r+2q conflict-free
#define SSB 132    // [k][n] stride (NN-B): banks 4k+n -> 8q+4d+r conflict-free

__device__ float g_qkv[4096 * 1024];
__device__ float g_M[512 * 512];
__device__ float g_Vp[4096 * 512];
__device__ float g_l1[2 * 2048 * 2048];
__device__ float g_l2[2 * 2048 * 2048];
__device__ float g_lambda;
__device__ float g_cvec[512];

// split two fp32 (x = k even, y = k odd) into packed bf16x2 hi and lo
__device__ __forceinline__ void split2(float x, float y, uint32_t& h, uint32_t& l) {
    asm("cvt.rn.bf16x2.f32 %0, %1, %2;" : "=r"(h) : "f"(y), "f"(x));
    float hx = __uint_as_float(h << 16);
    float hy = __uint_as_float(h & 0xffff0000u);
    asm("cvt.rn.bf16x2.f32 %0, %1, %2;" : "=r"(l) : "f"(y - hy), "f"(x - hx));
}

__device__ __forceinline__ void mma_bf16(float c[4],
                                         uint32_t a0, uint32_t a1, uint32_t a2, uint32_t a3,
                                         uint32_t b0, uint32_t b1) {
    asm volatile(
        "mma.sync.aligned.m16n8k16.row.col.f32.bf16.bf16.f32 "
        "{%0,%1,%2,%3}, {%4,%5,%6,%7}, {%8,%9}, {%0,%1,%2,%3};"
        : "+f"(c[0]), "+f"(c[1]), "+f"(c[2]), "+f"(c[3])
        : "r"(a0), "r"(a1), "r"(a2), "r"(a3), "r"(b0), "r"(b1));
}

__device__ __forceinline__ void cpa16(uint32_t smem, const void* gmem) {
    asm volatile("cp.async.ca.shared.global [%0], [%1], 16;" :: "r"(smem), "l"(gmem));
}
__device__ __forceinline__ void cpa_commit() {
    asm volatile("cp.async.commit_group;");
}
template <int N>
__device__ __forceinline__ void cpa_wait() {
    asm volatile("cp.async.wait_group %0;" :: "n"(N));
}

// ---------------------------------------------------------------------------
// bf16x2 GEMM, 2-stage cp.async pipeline. C = alpha*A@B(^T) (+bias).
// grid.z = batch*splitk. splitk>1: atomicAdd into zeroed C, bias by chunk 0.
// Calt: logits merge — z in [0,2) -> C batch z; z in [2,4) -> Calt, A/B +selOff.
// ---------------------------------------------------------------------------
template <bool TB>
__global__ __launch_bounds__(NTH, 1) void mma_gemm(
    const float* __restrict__ A, const float* __restrict__ B,
    float* __restrict__ C, float* __restrict__ Calt,
    int K, int lda, int ldb, int ldc,
    long long sA, long long sB, long long sC,
    float alpha, const float* __restrict__ bias, int splitk, int selOff)
{
    int zb = blockIdx.z / splitk;
    const int kchunk = blockIdx.z % splitk;
    if (Calt) {
        int sel = zb >> 1;
        zb &= 1;
        if (sel) { A += selOff; B += selOff; C = Calt; }
    }
    const int kc = K / splitk;
    const int kbeg = kchunk * kc;

    A += (long long)zb * sA;
    B += (long long)zb * sB;
    C += (long long)zb * sC;

    const int brow = blockIdx.y * BM;
    const int bcol = blockIdx.x * BN;
    const int t = threadIdx.x;
    const int lane = t & 31;
    const int wid = t >> 5;
    const int wm = (wid >> 2) * 64;
    const int wn = (wid & 3) * 32;
    const int q = lane & 3;
    const int r = lane >> 2;

    __shared__ __align__(16) float As[2][BM * SSA];   // raw fp32 [m][k], stride 24
    __shared__ __align__(16) float Bs[2][BM * SSA];   // TB:[n][k]/24, NN:[k][n]/132

    const uint32_t sa_base = (uint32_t)__cvta_generic_to_shared(&As[0][0]);
    const uint32_t sb_base = (uint32_t)__cvta_generic_to_shared(&Bs[0][0]);

    float acc[4][4][4];
#pragma unroll
    for (int i = 0; i < 4; i++)
#pragma unroll
        for (int j = 0; j < 4; j++)
#pragma unroll
            for (int c = 0; c < 4; c++) acc[i][j][c] = 0.f;

    // cp.async chunk mappings
    const int am  = t >> 2;          // A/TB-B row 0..63 (+64)
    const int akq = (t & 3) * 4;     // k offset (16B chunk)
    const int bkr = t >> 5;          // NN-B k row 0..7 (+8)
    const int bnc = (t & 31) * 4;    // NN-B n offset

    auto load_stage = [&](int st, int k0) {
        uint32_t sa = sa_base + (uint32_t)(st * BM * SSA * 4);
        uint32_t sb = sb_base + (uint32_t)(st * BM * SSA * 4);
#pragma unroll
        for (int i = 0; i < 2; i++) {
            int m = am + i * 64;
            cpa16(sa + (uint32_t)((m * SSA + akq) * 4),
                  &A[(long long)(brow + m) * lda + k0 + akq]);
        }
        if (!TB) {
#pragma unroll
            for (int i = 0; i < 2; i++) {
                int kk = bkr + i * 8;
                cpa16(sb + (uint32_t)((kk * SSB + bnc) * 4),
                      &B[(long long)(k0 + kk) * ldb + bcol + bnc]);
            }
        } else {
#pragma unroll
            for (int i = 0; i < 2; i++) {
                int n = am + i * 64;
                cpa16(sb + (uint32_t)((n * SSA + akq) * 4),
                      &B[(long long)(bcol + n) * ldb + k0 + akq]);
            }
        }
        cpa_commit();
    };

    const int nIter = kc / BK;
    load_stage(0, kbeg);

    for (int it = 0; it < nIter; it++) {
        if (it + 1 < nIter) {
            load_stage((it + 1) & 1, kbeg + (it + 1) * BK);
            cpa_wait<1>();
        } else {
            cpa_wait<0>();
        }
        __syncthreads();

        const float* As_ = As[it & 1];
        const float* Bs_ = Bs[it & 1];

        // B fragments: b0 = k{2q,2q+1}, b1 = k{2q+8,2q+9}, col n = wn+nt*8+r
        uint32_t Bh[4][2], Bl[4][2];
#pragma unroll
        for (int nt = 0; nt < 4; nt++) {
            int n = wn + nt * 8 + r;
            float x0, x1, x2, x3;
            if (TB) {
                float2 u0 = *(const float2*)&Bs_[n * SSA + 2 * q];
                float2 u1 = *(const float2*)&Bs_[n * SSA + 2 * q + 8];
                x0 = u0.x; x1 = u0.y; x2 = u1.x; x3 = u1.y;
            } else {
                x0 = Bs_[(2 * q) * SSB + n];
                x1 = Bs_[(2 * q + 1) * SSB + n];
                x2 = Bs_[(2 * q + 8) * SSB + n];
                x3 = Bs_[(2 * q + 9) * SSB + n];
            }
            split2(x0, x1, Bh[nt][0], Bl[nt][0]);
            split2(x2, x3, Bh[nt][1], Bl[nt][1]);
        }

        // A fragments per mt: a0=(r,2q..), a1=(r+8,2q..), a2=(r,2q+8..), a3=(r+8,2q+8..)
#pragma unroll
        for (int mt = 0; mt < 4; mt++) {
            int m = wm + mt * 16 + r;
            float2 p0 = *(const float2*)&As_[m * SSA + 2 * q];
            float2 p1 = *(const float2*)&As_[(m + 8) * SSA + 2 * q];
            float2 p2 = *(const float2*)&As_[m * SSA + 2 * q + 8];
            float2 p3 = *(const float2*)&As_[(m + 8) * SSA + 2 * q + 8];
            uint32_t Ah0, Ah1, Ah2, Ah3, Al0, Al1, Al2, Al3;
            split2(p0.x, p0.y, Ah0, Al0);
            split2(p1.x, p1.y, Ah1, Al1);
            split2(p2.x, p2.y, Ah2, Al2);
            split2(p3.x, p3.y, Ah3, Al3);
#pragma unroll
            for (int nt = 0; nt < 4; nt++) {
                mma_bf16(acc[mt][nt], Ah0, Ah1, Ah2, Ah3, Bh[nt][0], Bh[nt][1]);
                mma_bf16(acc[mt][nt], Ah0, Ah1, Ah2, Ah3, Bl[nt][0], Bl[nt][1]);
                mma_bf16(acc[mt][nt], Al0, Al1, Al2, Al3, Bh[nt][0], Bh[nt][1]);
            }
        }
        __syncthreads();
    }

    // epilogue
#pragma unroll
    for (int mt = 0; mt < 4; mt++) {
#pragma unroll
        for (int nt = 0; nt < 4; nt++) {
            int row = brow + wm + mt * 16 + r;
            int col = bcol + wn + nt * 8 + 2 * q;
            float b0 = 0.f, b1 = 0.f;
            if (bias && kchunk == 0) { b0 = bias[col]; b1 = bias[col + 1]; }
            float v0 = alpha * acc[mt][nt][0] + b0;
            float v1 = alpha * acc[mt][nt][1] + b1;
            float v2 = alpha * acc[mt][nt][2] + b0;
            float v3 = alpha * acc[mt][nt][3] + b1;
            if (splitk > 1) {
                atomicAdd(&C[(long long)row * ldc + col], v0);
                atomicAdd(&C[(long long)row * ldc + col + 1], v1);
                atomicAdd(&C[(long long)(row + 8) * ldc + col], v2);
                atomicAdd(&C[(long long)(row + 8) * ldc + col + 1], v3);
            } else {
                *(float2*)&C[(long long)row * ldc + col] = make_float2(v0, v1);
                *(float2*)&C[(long long)(row + 8) * ldc + col] = make_float2(v2, v3);
            }
        }
    }
}

// ---------------------------------------------------------------------------
__global__ void lambda_kernel(const float* __restrict__ lq1, const float* __restrict__ lk1,
                              const float* __restrict__ lq2, const float* __restrict__ lk2)
{
    if (threadIdx.x == 0) {
        float d1 = 0.f, d2 = 0.f;
        for (int i = 0; i < 64; i++) {
            d1 += lq1[i] * lk1[i];
            d2 += lq2[i] * lk2[i];
        }
        g_lambda = expf(d1) - expf(d2) + (0.8f - 0.6f * expf(-0.3f * 0.0f));
    }
}

// cvec[n] = bo[n] + (1-lam) * sum_k bv[k]*Wo[k,n]
__global__ void cvec_kernel(const float* __restrict__ bv, const float* __restrict__ Wo,
                            const float* __restrict__ bo)
{
    int n = blockIdx.x * blockDim.x + threadIdx.x;
    if (n < 512) {
        float s = 0.f;
        for (int k = 0; k < 8192; k++) s += bv[k] * Wo[(long long)k * 512 + n];
        g_cvec[n] = bo[n] + (1.f - g_lambda) * s;
    }
}

// ---------------------------------------------------------------------------
// Fused dual softmax + differential combine (rows of length 2048).
// ---------------------------------------------------------------------------
__global__ __launch_bounds__(256) void softmax_diff_kernel(
    const float* __restrict__ l1, const float* __restrict__ l2,
    float* __restrict__ out, int S)
{
    long long row = blockIdx.x;
    const float* r1 = l1 + row * S;
    const float* r2 = l2 + row * S;
    float* ro = out + row * S;
    const int t = threadIdx.x;
    const int lane = t & 31, warp = t >> 5;

    float v1[8], v2[8];
#pragma unroll
    for (int i = 0; i < 8; i++) {
        v1[i] = r1[t + i * 256];
        v2[i] = r2[t + i * 256];
    }

    float m1 = -1e30f, m2 = -1e30f;
#pragma unroll
    for (int i = 0; i < 8; i++) {
        m1 = fmaxf(m1, v1[i]);
        m2 = fmaxf(m2, v2[i]);
    }
#pragma unroll
    for (int o = 16; o; o >>= 1) {
        m1 = fmaxf(m1, __shfl_xor_sync(0xffffffffu, m1, o));
        m2 = fmaxf(m2, __shfl_xor_sync(0xffffffffu, m2, o));
    }
    __shared__ float s1[8], s2[8];
    if (lane == 0) { s1[warp] = m1; s2[warp] = m2; }
    __syncthreads();
    m1 = s1[0]; m2 = s2[0];
#pragma unroll
    for (int w = 1; w < 8; w++) {
        m1 = fmaxf(m1, s1[w]);
        m2 = fmaxf(m2, s2[w]);
    }

    float e1[8], e2[8];
    float sum1 = 0.f, sum2 = 0.f;
#pragma unroll
    for (int i = 0; i < 8; i++) {
        e1[i] = __expf(v1[i] - m1);
        e2[i] = __expf(v2[i] - m2);
        sum1 += e1[i];
        sum2 += e2[i];
    }
#pragma unroll
    for (int o = 16; o; o >>= 1) {
        sum1 += __shfl_xor_sync(0xffffffffu, sum1, o);
        sum2 += __shfl_xor_sync(0xffffffffu, sum2, o);
    }
    __syncthreads();
    if (lane == 0) { s1[warp] = sum1; s2[warp] = sum2; }
    __syncthreads();
    sum1 = 0.f; sum2 = 0.f;
#pragma unroll
    for (int w = 0; w < 8; w++) { sum1 += s1[w]; sum2 += s2[w]; }

    const float inv1 = 1.f / sum1;
    const float inv2 = g_lambda / sum2;
#pragma unroll
    for (int i = 0; i < 8; i++)
        ro[t + i * 256] = e1[i] * inv1 - e2[i] * inv2;
}

// ---------------------------------------------------------------------------
extern "C" void kernel_launch(void* const* d_in, const int* in_sizes, int n_in,
                              void* d_out, int out_size)
{
    const float* x    = (const float*)d_in[0];
    const float* Wqkv = (const float*)d_in[1];
    const float* bqkv = (const float*)d_in[2];
    const float* Wv   = (const float*)d_in[3];
    const float* bv   = (const float*)d_in[4];
    const float* Wo   = (const float*)d_in[5];
    const float* bo   = (const float*)d_in[6];
    const float* lq1  = (const float*)d_in[7];
    const float* lk1  = (const float*)d_in[8];
    const float* lq2  = (const float*)d_in[9];
    const float* lk2  = (const float*)d_in[10];
    float* out = (float*)d_out;

    float *qkv, *Mm, *Vp, *l1, *l2, *cvec;
    cudaGetSymbolAddress((void**)&qkv,  g_qkv);
    cudaGetSymbolAddress((void**)&Mm,   g_M);
    cudaGetSymbolAddress((void**)&Vp,   g_Vp);
    cudaGetSymbolAddress((void**)&l1,   g_l1);
    cudaGetSymbolAddress((void**)&l2,   g_l2);
    cudaGetSymbolAddress((void**)&cvec, g_cvec);

    const long long SQKV = 2048LL * 1024;
    const long long SLOG = 2048LL * 2048;
    const long long SVP  = 2048LL * 512;

    // 0) lambda scalar + folded bias vector
    lambda_kernel<<<1, 32>>>(lq1, lk1, lq2, lk2);
    cvec_kernel<<<2, 256>>>(bv, Wo, bo);

    // 1) qkv = x @ Wqkv + bqkv        [4096,1024], K=512
    mma_gemm<false><<<dim3(1024 / BN, 4096 / BM, 1), NTH>>>(
        x, Wqkv, qkv, nullptr, 512, 512, 1024, 1024, 0, 0, 0, 1.f, bqkv, 1, 0);

    // 2) M = Wv @ Wo                  [512,512], K=8192, splitK=16
    cudaMemsetAsync(Mm, 0, 512 * 512 * sizeof(float));
    mma_gemm<false><<<dim3(512 / BN, 512 / BM, 16), NTH>>>(
        Wv, Wo, Mm, nullptr, 8192, 8192, 512, 512, 0, 0, 0, 1.f, nullptr, 16, 0);

    // 3) V' = x @ M                   [4096,512], K=512, splitK=2
    cudaMemsetAsync(Vp, 0, 4096 * 512 * sizeof(float));
    mma_gemm<false><<<dim3(512 / BN, 4096 / BM, 2), NTH>>>(
        x, Mm, Vp, nullptr, 512, 512, 512, 512, 0, 0, 0, 1.f, nullptr, 2, 0);

    // 4) logits merged: z=0,1 -> l1 (Q1/K1); z=2,3 -> l2 (Q2/K2, offset +256)
    mma_gemm<true><<<dim3(2048 / BN, 2048 / BM, 4), NTH>>>(
        qkv + 0, qkv + 512, l1, l2, 256, 1024, 1024, 2048,
        SQKV, SQKV, SLOG, 0.125f, nullptr, 1, 256);

    // 5) diff = softmax(l1) - lam*softmax(l2)   (in place over l1)
    softmax_diff_kernel<<<4096, 256>>>(l1, l2, l1, 2048);

    // 6) out = diff @ V' + cvec       [2][2048,512], K=2048, splitK=2
    cudaMemsetAsync(out, 0, 2 * 2048 * 512 * sizeof(float));
    mma_gemm<false><<<dim3(512 / BN, 2048 / BM, 4), NTH>>>(
        l1, Vp, out, nullptr, 2048, 2048, 512, 512,
        SLOG, SVP, SVP, 1.f, cvec, 2, 0);
}

// round 8
// speedup vs baseline: 2.2853x; 1.0078x over previous
#include <cuda_runtime.h>
#include <cuda_bf16.h>
#include <math.h>
#include <stdint.h>

// ---------------------------------------------------------------------------
// DifferentialAttention, folded algebra, 3-pass bf16 (hi/lo plane) GEMMs.
// All operands pre-split into bf16 hi+lo planes (inputs by split kernels,
// intermediates split in producer epilogues). GEMM mainloop is a pure bf16
// ldmatrix + mma pipeline (3-stage cp.async), 3 MMA passes (hh, hl, lh).
//   qkv  = x @ Wqkv + bqkv          -> planes      [4096,1024]
//   M    = Wv @ Wo                  -> fp32 (splitK=16) -> planes [512,512]
//   V'   = x @ M                    -> planes      [4096,512]
//   l1/l2 = Q@K^T * 0.125           -> fp32 (merged z=4)
//   diff = softmax(l1)-lam*softmax(l2) -> planes   [2][2048,2048]
//   out  = diff @ V' + cvec         -> fp32 (splitK=2)
// ---------------------------------------------------------------------------

#define BM 128
#define BN 128
#define BK 16
#define NTH 256
#define NSTAGE 3
#define STAGE_BYTES 16384   // A: 2 planes x 4KB, B: 2 planes x 4KB

typedef __nv_bfloat16 bf16;

// fp32 scratch
__device__ float g_M[512 * 512];
__device__ float g_l1[2 * 2048 * 2048];
__device__ float g_l2[2 * 2048 * 2048];
__device__ float g_lambda;
__device__ float g_cvec[512];
// bf16 hi/lo planes
__device__ bf16 g_xh[4096 * 512],  g_xl[4096 * 512];
__device__ bf16 g_wqh[512 * 1024], g_wql[512 * 1024];
__device__ bf16 g_wvh[512 * 8192], g_wvl[512 * 8192];
__device__ bf16 g_woh[8192 * 512], g_wol[8192 * 512];
__device__ bf16 g_qh[4096 * 1024], g_ql[4096 * 1024];
__device__ bf16 g_mh[512 * 512],   g_ml[512 * 512];
__device__ bf16 g_vph[4096 * 512], g_vpl[4096 * 512];
__device__ bf16 g_dh[2 * 2048 * 2048], g_dl[2 * 2048 * 2048];

// split two fp32 (x = even idx, y = odd idx) into packed bf16x2 hi and lo
__device__ __forceinline__ void split2(float x, float y, uint32_t& h, uint32_t& l) {
    asm("cvt.rn.bf16x2.f32 %0, %1, %2;" : "=r"(h) : "f"(y), "f"(x));
    float hx = __uint_as_float(h << 16);
    float hy = __uint_as_float(h & 0xffff0000u);
    asm("cvt.rn.bf16x2.f32 %0, %1, %2;" : "=r"(l) : "f"(y - hy), "f"(x - hx));
}

__device__ __forceinline__ void mma_bf16(float c[4],
                                         uint32_t a0, uint32_t a1, uint32_t a2, uint32_t a3,
                                         uint32_t b0, uint32_t b1) {
    asm volatile(
        "mma.sync.aligned.m16n8k16.row.col.f32.bf16.bf16.f32 "
        "{%0,%1,%2,%3}, {%4,%5,%6,%7}, {%8,%9}, {%0,%1,%2,%3};"
        : "+f"(c[0]), "+f"(c[1]), "+f"(c[2]), "+f"(c[3])
        : "r"(a0), "r"(a1), "r"(a2), "r"(a3), "r"(b0), "r"(b1));
}

__device__ __forceinline__ void ldsm_x4(uint32_t& r0, uint32_t& r1, uint32_t& r2, uint32_t& r3,
                                        uint32_t addr) {
    asm volatile("ldmatrix.sync.aligned.m8n8.x4.shared.b16 {%0,%1,%2,%3}, [%4];"
                 : "=r"(r0), "=r"(r1), "=r"(r2), "=r"(r3) : "r"(addr));
}
__device__ __forceinline__ void ldsm_x4t(uint32_t& r0, uint32_t& r1, uint32_t& r2, uint32_t& r3,
                                         uint32_t addr) {
    asm volatile("ldmatrix.sync.aligned.m8n8.x4.trans.shared.b16 {%0,%1,%2,%3}, [%4];"
                 : "=r"(r0), "=r"(r1), "=r"(r2), "=r"(r3) : "r"(addr));
}

__device__ __forceinline__ void cpa16(uint32_t smem, const void* gmem) {
    asm volatile("cp.async.ca.shared.global [%0], [%1], 16;" :: "r"(smem), "l"(gmem));
}
__device__ __forceinline__ void cpa_commit() { asm volatile("cp.async.commit_group;"); }
template <int N>
__device__ __forceinline__ void cpa_wait() { asm volatile("cp.async.wait_group %0;" :: "n"(N)); }

// ---------------------------------------------------------------------------
// 3-pass bf16 GEMM over hi/lo planes. 3-stage cp.async pipeline.
// Output: Ch!=null -> bf16 plane store (splitk must be 1);
//         else splitk>1 -> fp32 atomicAdd; else fp32 store.
// Calt: merged logits (z in [2,4) -> A/B + selOff, C -> Calt).
// smem per stage: A at +0 (plane*4096 + m*32 + swz16), 8KB;
//                 B at +8192: TB same as A; NN plane*4096 + k*256 + swz16.
// ---------------------------------------------------------------------------
template <bool TB>
__global__ __launch_bounds__(NTH, 1) void bf_gemm(
    const bf16* __restrict__ Ah, const bf16* __restrict__ Al,
    const bf16* __restrict__ Bh, const bf16* __restrict__ Bl,
    float* __restrict__ C, float* __restrict__ Calt,
    bf16* __restrict__ Ch, bf16* __restrict__ Cl,
    int K, int lda, int ldb, int ldc,
    long long sA, long long sB, long long sC,
    float alpha, const float* __restrict__ bias, int splitk, int selOff)
{
    int zb = blockIdx.z / splitk;
    const int kchunk = blockIdx.z % splitk;
    if (Calt) {
        int sel = zb >> 1;
        zb &= 1;
        if (sel) { Ah += selOff; Al += selOff; Bh += selOff; Bl += selOff; C = Calt; }
    }
    const int kc = K / splitk;
    const int kbeg = kchunk * kc;

    Ah += (long long)zb * sA; Al += (long long)zb * sA;
    Bh += (long long)zb * sB; Bl += (long long)zb * sB;
    if (C) C += (long long)zb * sC;
    if (Ch) { Ch += (long long)zb * sC; Cl += (long long)zb * sC; }

    const int brow = blockIdx.y * BM;
    const int bcol = blockIdx.x * BN;
    const int t = threadIdx.x;
    const int lane = t & 31;
    const int wid = t >> 5;
    const int wm = (wid >> 2) * 64;
    const int wn = (wid & 3) * 32;
    const int q = lane & 3;
    const int r = lane >> 2;
    const int lg = lane >> 3;      // ldmatrix group 0..3
    const int lr = lane & 7;

    __shared__ __align__(128) char sm[NSTAGE][STAGE_BYTES];
    const uint32_t sm0 = (uint32_t)__cvta_generic_to_shared(&sm[0][0]);

    float acc[4][4][4];
#pragma unroll
    for (int i = 0; i < 4; i++)
#pragma unroll
        for (int j = 0; j < 4; j++)
#pragma unroll
            for (int c = 0; c < 4; c++) acc[i][j][c] = 0.f;

    // cp.async mappings: 512 chunks of 16B per operand per stage, 2/thread each.
    // A (and TB-B): idx -> plane = idx>>8, m = (idx&255)>>1, half = idx&1
    // NN-B:         idx -> plane = idx>>8, k = (idx&255)>>4, j = idx&15
    auto load_stage = [&](int st, int k0) {
        uint32_t base = sm0 + (uint32_t)(st * STAGE_BYTES);
#pragma unroll
        for (int i = 0; i < 2; i++) {
            int idx = t + i * 256;
            int pl = idx >> 8, rem = idx & 255;
            int m = rem >> 1, half = rem & 1;
            const bf16* src = (pl ? Al : Ah) + (long long)(brow + m) * lda + k0 + half * 8;
            cpa16(base + (uint32_t)(pl * 4096 + m * 32 + ((half ^ ((m >> 2) & 1)) * 16)), src);
        }
#pragma unroll
        for (int i = 0; i < 2; i++) {
            int idx = t + i * 256;
            int pl = idx >> 8, rem = idx & 255;
            if (TB) {
                int n = rem >> 1, half = rem & 1;
                const bf16* src = (pl ? Bl : Bh) + (long long)(bcol + n) * ldb + k0 + half * 8;
                cpa16(base + (uint32_t)(8192 + pl * 4096 + n * 32 + ((half ^ ((n >> 2) & 1)) * 16)), src);
            } else {
                int kk = rem >> 4, j = rem & 15;
                const bf16* src = (pl ? Bl : Bh) + (long long)(k0 + kk) * ldb + bcol + j * 8;
                cpa16(base + (uint32_t)(8192 + pl * 4096 + kk * 256 + ((j ^ (kk & 7)) * 16)), src);
            }
        }
        cpa_commit();
    };

    const int nIter = kc / BK;
    load_stage(0, kbeg);
    load_stage(1, kbeg + BK);

    for (int it = 0; it < nIter; it++) {
        if (it + 1 < nIter) cpa_wait<1>(); else cpa_wait<0>();
        __syncthreads();
        if (it + 2 < nIter) load_stage((it + 2) % NSTAGE, kbeg + (it + 2) * BK);

        uint32_t base = sm0 + (uint32_t)((it % NSTAGE) * STAGE_BYTES);

        // ---- B fragments (2 planes x 4 nt x 2 regs) ----
        uint32_t Bf[2][4][2];
#pragma unroll
        for (int pl = 0; pl < 2; pl++) {
#pragma unroll
            for (int pair = 0; pair < 2; pair++) {
                int nl = pair * 2, nh = pair * 2 + 1;
                if (TB) {
                    int row = wn + pair * 16 + lr + (lg & 1) * 8;
                    int half = lg >> 1;
                    uint32_t a = base + (uint32_t)(8192 + pl * 4096 + row * 32 +
                                                   ((half ^ ((row >> 2) & 1)) * 16));
                    ldsm_x4(Bf[pl][nl][0], Bf[pl][nh][0], Bf[pl][nl][1], Bf[pl][nh][1], a);
                } else {
                    int krow = lr + (lg & 1) * 8;
                    int j = (wn >> 3) + pair * 2 + (lg >> 1);
                    uint32_t a = base + (uint32_t)(8192 + pl * 4096 + krow * 256 +
                                                   ((j ^ (krow & 7)) * 16));
                    ldsm_x4t(Bf[pl][nl][0], Bf[pl][nl][1], Bf[pl][nh][0], Bf[pl][nh][1], a);
                }
            }
        }

        // ---- A fragments per mt, 3 MMA passes ----
#pragma unroll
        for (int mt = 0; mt < 4; mt++) {
            int row = wm + mt * 16 + lr + (lg & 1) * 8;
            int half = lg >> 1;
            uint32_t swz = (uint32_t)((half ^ ((row >> 2) & 1)) * 16);
            uint32_t Ah0, Ah1, Ah2, Ah3, Al0, Al1, Al2, Al3;
            ldsm_x4(Ah0, Ah1, Ah2, Ah3, base + (uint32_t)(row * 32) + swz);
            ldsm_x4(Al0, Al1, Al2, Al3, base + (uint32_t)(4096 + row * 32) + swz);
#pragma unroll
            for (int nt = 0; nt < 4; nt++) {
                mma_bf16(acc[mt][nt], Ah0, Ah1, Ah2, Ah3, Bf[0][nt][0], Bf[0][nt][1]);
                mma_bf16(acc[mt][nt], Ah0, Ah1, Ah2, Ah3, Bf[1][nt][0], Bf[1][nt][1]);
                mma_bf16(acc[mt][nt], Al0, Al1, Al2, Al3, Bf[0][nt][0], Bf[0][nt][1]);
            }
        }
    }

    // ---- epilogue ----
#pragma unroll
    for (int mt = 0; mt < 4; mt++) {
#pragma unroll
        for (int nt = 0; nt < 4; nt++) {
            int row = brow + wm + mt * 16 + r;
            int col = bcol + wn + nt * 8 + 2 * q;
            float b0 = 0.f, b1 = 0.f;
            if (bias && kchunk == 0) { b0 = bias[col]; b1 = bias[col + 1]; }
            float v0 = alpha * acc[mt][nt][0] + b0;
            float v1 = alpha * acc[mt][nt][1] + b1;
            float v2 = alpha * acc[mt][nt][2] + b0;
            float v3 = alpha * acc[mt][nt][3] + b1;
            if (Ch) {
                uint32_t h, l;
                split2(v0, v1, h, l);
                *(uint32_t*)&Ch[(long long)row * ldc + col] = h;
                *(uint32_t*)&Cl[(long long)row * ldc + col] = l;
                split2(v2, v3, h, l);
                *(uint32_t*)&Ch[(long long)(row + 8) * ldc + col] = h;
                *(uint32_t*)&Cl[(long long)(row + 8) * ldc + col] = l;
            } else if (splitk > 1) {
                atomicAdd(&C[(long long)row * ldc + col], v0);
                atomicAdd(&C[(long long)row * ldc + col + 1], v1);
                atomicAdd(&C[(long long)(row + 8) * ldc + col], v2);
                atomicAdd(&C[(long long)(row + 8) * ldc + col + 1], v3);
            } else {
                *(float2*)&C[(long long)row * ldc + col] = make_float2(v0, v1);
                *(float2*)&C[(long long)(row + 8) * ldc + col] = make_float2(v2, v3);
            }
        }
    }
}

// ---------------------------------------------------------------------------
// Elementwise fp32 -> bf16 hi/lo plane split (n4 = count of float4)
// ---------------------------------------------------------------------------
__global__ void split_kernel(const float4* __restrict__ src,
                             uint2* __restrict__ h, uint2* __restrict__ l, int n4)
{
    int i = blockIdx.x * blockDim.x + threadIdx.x;
    if (i < n4) {
        float4 v = src[i];
        uint32_t h0, l0, h1, l1;
        split2(v.x, v.y, h0, l0);
        split2(v.z, v.w, h1, l1);
        h[i] = make_uint2(h0, h1);
        l[i] = make_uint2(l0, l1);
    }
}

// ---------------------------------------------------------------------------
__global__ void lambda_kernel(const float* __restrict__ lq1, const float* __restrict__ lk1,
                              const float* __restrict__ lq2, const float* __restrict__ lk2)
{
    if (threadIdx.x == 0) {
        float d1 = 0.f, d2 = 0.f;
        for (int i = 0; i < 64; i++) {
            d1 += lq1[i] * lk1[i];
            d2 += lq2[i] * lk2[i];
        }
        g_lambda = expf(d1) - expf(d2) + (0.8f - 0.6f * expf(-0.3f * 0.0f));
    }
}

// cvec[n] = bo[n] + (1-lam) * sum_k bv[k]*Wo[k,n]
__global__ void cvec_kernel(const float* __restrict__ bv, const float* __restrict__ Wo,
                            const float* __restrict__ bo)
{
    int n = blockIdx.x * blockDim.x + threadIdx.x;
    if (n < 512) {
        float s = 0.f;
        for (int k = 0; k < 8192; k++) s += bv[k] * Wo[(long long)k * 512 + n];
        g_cvec[n] = bo[n] + (1.f - g_lambda) * s;
    }
}

// ---------------------------------------------------------------------------
// Fused dual softmax + differential combine; writes bf16 hi/lo planes.
// One block per row (2048 cols); thread t owns cols [8t, 8t+8).
// ---------------------------------------------------------------------------
__global__ __launch_bounds__(256) void softmax_diff_kernel(
    const float* __restrict__ l1, const float* __restrict__ l2,
    bf16* __restrict__ dh, bf16* __restrict__ dl)
{
    long long row = blockIdx.x;
    const float* r1 = l1 + row * 2048;
    const float* r2 = l2 + row * 2048;
    const int t = threadIdx.x;
    const int lane = t & 31, warp = t >> 5;

    float v1[8], v2[8];
    *(float4*)&v1[0] = *(const float4*)&r1[t * 8];
    *(float4*)&v1[4] = *(const float4*)&r1[t * 8 + 4];
    *(float4*)&v2[0] = *(const float4*)&r2[t * 8];
    *(float4*)&v2[4] = *(const float4*)&r2[t * 8 + 4];

    float m1 = -1e30f, m2 = -1e30f;
#pragma unroll
    for (int i = 0; i < 8; i++) {
        m1 = fmaxf(m1, v1[i]);
        m2 = fmaxf(m2, v2[i]);
    }
#pragma unroll
    for (int o = 16; o; o >>= 1) {
        m1 = fmaxf(m1, __shfl_xor_sync(0xffffffffu, m1, o));
        m2 = fmaxf(m2, __shfl_xor_sync(0xffffffffu, m2, o));
    }
    __shared__ float s1[8], s2[8];
    if (lane == 0) { s1[warp] = m1; s2[warp] = m2; }
    __syncthreads();
    m1 = s1[0]; m2 = s2[0];
#pragma unroll
    for (int w = 1; w < 8; w++) {
        m1 = fmaxf(m1, s1[w]);
        m2 = fmaxf(m2, s2[w]);
    }

    float e1[8], e2[8];
    float sum1 = 0.f, sum2 = 0.f;
#pragma unroll
    for (int i = 0; i < 8; i++) {
        e1[i] = __expf(v1[i] - m1);
        e2[i] = __expf(v2[i] - m2);
        sum1 += e1[i];
        sum2 += e2[i];
    }
#pragma unroll
    for (int o = 16; o; o >>= 1) {
        sum1 += __shfl_xor_sync(0xffffffffu, sum1, o);
        sum2 += __shfl_xor_sync(0xffffffffu, sum2, o);
    }
    __syncthreads();
    if (lane == 0) { s1[warp] = sum1; s2[warp] = sum2; }
    __syncthreads();
    sum1 = 0.f; sum2 = 0.f;
#pragma unroll
    for (int w = 0; w < 8; w++) { sum1 += s1[w]; sum2 += s2[w]; }

    const float inv1 = 1.f / sum1;
    const float inv2 = g_lambda / sum2;
    uint4 hv, lv;
    float d0, d1v;
    d0 = e1[0] * inv1 - e2[0] * inv2; d1v = e1[1] * inv1 - e2[1] * inv2;
    split2(d0, d1v, hv.x, lv.x);
    d0 = e1[2] * inv1 - e2[2] * inv2; d1v = e1[3] * inv1 - e2[3] * inv2;
    split2(d0, d1v, hv.y, lv.y);
    d0 = e1[4] * inv1 - e2[4] * inv2; d1v = e1[5] * inv1 - e2[5] * inv2;
    split2(d0, d1v, hv.z, lv.z);
    d0 = e1[6] * inv1 - e2[6] * inv2; d1v = e1[7] * inv1 - e2[7] * inv2;
    split2(d0, d1v, hv.w, lv.w);
    *(uint4*)&dh[row * 2048 + t * 8] = hv;
    *(uint4*)&dl[row * 2048 + t * 8] = lv;
}

// ---------------------------------------------------------------------------
extern "C" void kernel_launch(void* const* d_in, const int* in_sizes, int n_in,
                              void* d_out, int out_size)
{
    const float* x    = (const float*)d_in[0];
    const float* Wqkv = (const float*)d_in[1];
    const float* bqkv = (const float*)d_in[2];
    const float* Wv   = (const float*)d_in[3];
    const float* bv   = (const float*)d_in[4];
    const float* Wo   = (const float*)d_in[5];
    const float* bo   = (const float*)d_in[6];
    const float* lq1  = (const float*)d_in[7];
    const float* lk1  = (const float*)d_in[8];
    const float* lq2  = (const float*)d_in[9];
    const float* lk2  = (const float*)d_in[10];
    float* out = (float*)d_out;

    float *Mm, *l1, *l2, *cvec;
    bf16 *xh, *xl, *wqh, *wql, *wvh, *wvl, *woh, *wol;
    bf16 *qh, *ql, *mh, *ml, *vph, *vpl, *dh, *dl;
    cudaGetSymbolAddress((void**)&Mm,  g_M);
    cudaGetSymbolAddress((void**)&l1,  g_l1);
    cudaGetSymbolAddress((void**)&l2,  g_l2);
    cudaGetSymbolAddress((void**)&cvec, g_cvec);
    cudaGetSymbolAddress((void**)&xh,  g_xh);   cudaGetSymbolAddress((void**)&xl,  g_xl);
    cudaGetSymbolAddress((void**)&wqh, g_wqh);  cudaGetSymbolAddress((void**)&wql, g_wql);
    cudaGetSymbolAddress((void**)&wvh, g_wvh);  cudaGetSymbolAddress((void**)&wvl, g_wvl);
    cudaGetSymbolAddress((void**)&woh, g_woh);  cudaGetSymbolAddress((void**)&wol, g_wol);
    cudaGetSymbolAddress((void**)&qh,  g_qh);   cudaGetSymbolAddress((void**)&ql,  g_ql);
    cudaGetSymbolAddress((void**)&mh,  g_mh);   cudaGetSymbolAddress((void**)&ml,  g_ml);
    cudaGetSymbolAddress((void**)&vph, g_vph);  cudaGetSymbolAddress((void**)&vpl, g_vpl);
    cudaGetSymbolAddress((void**)&dh,  g_dh);   cudaGetSymbolAddress((void**)&dl,  g_dl);

    const long long SQ  = 2048LL * 1024;   // qkv plane batch stride
    const long long SL  = 2048LL * 2048;   // logits / diff batch stride
    const long long SV  = 2048LL * 512;    // V' / out batch stride

    // 0) scalars + input splits
    lambda_kernel<<<1, 32>>>(lq1, lk1, lq2, lk2);
    cvec_kernel<<<2, 256>>>(bv, Wo, bo);
    split_kernel<<<2048, 256>>>((const float4*)x,    (uint2*)xh,  (uint2*)xl,  4096 * 512 / 4);
    split_kernel<<<512,  256>>>((const float4*)Wqkv, (uint2*)wqh, (uint2*)wql, 512 * 1024 / 4);
    split_kernel<<<4096, 256>>>((const float4*)Wv,   (uint2*)wvh, (uint2*)wvl, 512 * 8192 / 4);
    split_kernel<<<4096, 256>>>((const float4*)Wo,   (uint2*)woh, (uint2*)wol, 8192 * 512 / 4);

    // 1) qkv = x @ Wqkv + bqkv -> planes  [4096,1024]
    bf_gemm<false><<<dim3(8, 32, 1), NTH>>>(
        xh, xl, wqh, wql, nullptr, nullptr, qh, ql,
        512, 512, 1024, 1024, 0, 0, 0, 1.f, bqkv, 1, 0);

    // 2) M = Wv @ Wo  (fp32, splitK=16), then split to planes
    cudaMemsetAsync(Mm, 0, 512 * 512 * sizeof(float));
    bf_gemm<false><<<dim3(4, 4, 16), NTH>>>(
        wvh, wvl, woh, wol, Mm, nullptr, nullptr, nullptr,
        8192, 8192, 512, 512, 0, 0, 0, 1.f, nullptr, 16, 0);
    split_kernel<<<256, 256>>>((const float4*)Mm, (uint2*)mh, (uint2*)ml, 512 * 512 / 4);

    // 3) V' = x @ M -> planes  [4096,512]
    bf_gemm<false><<<dim3(4, 32, 1), NTH>>>(
        xh, xl, mh, ml, nullptr, nullptr, vph, vpl,
        512, 512, 512, 512, 0, 0, 0, 1.f, nullptr, 1, 0);

    // 4) logits merged (z=0,1 -> l1 via Q1/K1; z=2,3 -> l2 via +256 offset)
    bf_gemm<true><<<dim3(16, 16, 4), NTH>>>(
        qh + 0, ql + 0, qh + 512, ql + 512, l1, l2, nullptr, nullptr,
        256, 1024, 1024, 2048, SQ, SQ, SL, 0.125f, nullptr, 1, 256);

    // 5) diff = softmax(l1) - lam*softmax(l2) -> planes
    softmax_diff_kernel<<<4096, 256>>>(l1, l2, dh, dl);

    // 6) out = diff @ V' + cvec  (fp32, splitK=2)
    cudaMemsetAsync(out, 0, 2 * 2048 * 512 * sizeof(float));
    bf_gemm<false><<<dim3(4, 16, 4), NTH>>>(
        dh, dl, vph, vpl, out, nullptr, nullptr, nullptr,
        2048, 2048, 512, 512, SL, SV, SV, 1.f, cvec, 2, 0);
}

// round 10
// speedup vs baseline: 5.3458x; 2.3392x over previous
#include <cuda_runtime.h>
#include <cuda_bf16.h>
#include <math.h>
#include <stdint.h>

// ---------------------------------------------------------------------------
// DifferentialAttention, folded algebra, 3-pass bf16 (hi/lo plane) GEMMs.
// R10 (= R9 resubmit): 512-thread CTAs (16 warps, 32x32 warp tiles) for
// 2x warps/SMSP; parallelized cvec. Mainloop: ldmatrix + mma, 3-stage cp.async.
//   qkv  = x @ Wqkv + bqkv          -> planes      [4096,1024]
//   M    = Wv @ Wo                  -> fp32 (splitK=16) -> planes [512,512]
//   V'   = x @ M                    -> planes      [4096,512]
//   l1/l2 = Q@K^T * 0.125           -> fp32 (merged z=4)
//   diff = softmax(l1)-lam*softmax(l2) -> planes   [2][2048,2048]
//   out  = diff @ V' + cvec         -> fp32 (splitK=2)
// ---------------------------------------------------------------------------

#define BM 128
#define BN 128
#define BK 16
#define NTH 512
#define NSTAGE 3
#define STAGE_BYTES 16384   // A: 2 planes x 4KB, B: 2 planes x 4KB

typedef __nv_bfloat16 bf16;

// fp32 scratch
__device__ float g_M[512 * 512];
__device__ float g_l1[2 * 2048 * 2048];
__device__ float g_l2[2 * 2048 * 2048];
__device__ float g_lambda;
__device__ float g_cvec[512];
// bf16 hi/lo planes
__device__ bf16 g_xh[4096 * 512],  g_xl[4096 * 512];
__device__ bf16 g_wqh[512 * 1024], g_wql[512 * 1024];
__device__ bf16 g_wvh[512 * 8192], g_wvl[512 * 8192];
__device__ bf16 g_woh[8192 * 512], g_wol[8192 * 512];
__device__ bf16 g_qh[4096 * 1024], g_ql[4096 * 1024];
__device__ bf16 g_mh[512 * 512],   g_ml[512 * 512];
__device__ bf16 g_vph[4096 * 512], g_vpl[4096 * 512];
__device__ bf16 g_dh[2 * 2048 * 2048], g_dl[2 * 2048 * 2048];

// split two fp32 (x = even idx, y = odd idx) into packed bf16x2 hi and lo
__device__ __forceinline__ void split2(float x, float y, uint32_t& h, uint32_t& l) {
    asm("cvt.rn.bf16x2.f32 %0, %1, %2;" : "=r"(h) : "f"(y), "f"(x));
    float hx = __uint_as_float(h << 16);
    float hy = __uint_as_float(h & 0xffff0000u);
    asm("cvt.rn.bf16x2.f32 %0, %1, %2;" : "=r"(l) : "f"(y - hy), "f"(x - hx));
}

__device__ __forceinline__ void mma_bf16(float c[4],
                                         uint32_t a0, uint32_t a1, uint32_t a2, uint32_t a3,
                                         uint32_t b0, uint32_t b1) {
    asm volatile(
        "mma.sync.aligned.m16n8k16.row.col.f32.bf16.bf16.f32 "
        "{%0,%1,%2,%3}, {%4,%5,%6,%7}, {%8,%9}, {%0,%1,%2,%3};"
        : "+f"(c[0]), "+f"(c[1]), "+f"(c[2]), "+f"(c[3])
        : "r"(a0), "r"(a1), "r"(a2), "r"(a3), "r"(b0), "r"(b1));
}

__device__ __forceinline__ void ldsm_x4(uint32_t& r0, uint32_t& r1, uint32_t& r2, uint32_t& r3,
                                        uint32_t addr) {
    asm volatile("ldmatrix.sync.aligned.m8n8.x4.shared.b16 {%0,%1,%2,%3}, [%4];"
                 : "=r"(r0), "=r"(r1), "=r"(r2), "=r"(r3) : "r"(addr));
}
__device__ __forceinline__ void ldsm_x4t(uint32_t& r0, uint32_t& r1, uint32_t& r2, uint32_t& r3,
                                         uint32_t addr) {
    asm volatile("ldmatrix.sync.aligned.m8n8.x4.trans.shared.b16 {%0,%1,%2,%3}, [%4];"
                 : "=r"(r0), "=r"(r1), "=r"(r2), "=r"(r3) : "r"(addr));
}

__device__ __forceinline__ void cpa16(uint32_t smem, const void* gmem) {
    asm volatile("cp.async.ca.shared.global [%0], [%1], 16;" :: "r"(smem), "l"(gmem));
}
__device__ __forceinline__ void cpa_commit() { asm volatile("cp.async.commit_group;"); }
template <int N>
__device__ __forceinline__ void cpa_wait() { asm volatile("cp.async.wait_group %0;" :: "n"(N)); }

// ---------------------------------------------------------------------------
// 3-pass bf16 GEMM over hi/lo planes. 512 threads, 16 warps (4x4 of 32x32).
// 3-stage cp.async pipeline. Output: Ch!=null -> bf16 plane store (splitk=1);
// else splitk>1 -> fp32 atomicAdd; else fp32 store.
// Calt: merged logits (z in [2,4) -> A/B + selOff, C -> Calt).
// smem per stage: A at +0 (plane*4096 + m*32 + swz16);
//                 B at +8192: TB same as A; NN plane*4096 + k*256 + swz16.
// ---------------------------------------------------------------------------
template <bool TB>
__global__ __launch_bounds__(NTH, 1) void bf_gemm(
    const bf16* __restrict__ Ah, const bf16* __restrict__ Al,
    const bf16* __restrict__ Bh, const bf16* __restrict__ Bl,
    float* __restrict__ C, float* __restrict__ Calt,
    bf16* __restrict__ Ch, bf16* __restrict__ Cl,
    int K, int lda, int ldb, int ldc,
    long long sA, long long sB, long long sC,
    float alpha, const float* __restrict__ bias, int splitk, int selOff)
{
    int zb = blockIdx.z / splitk;
    const int kchunk = blockIdx.z % splitk;
    if (Calt) {
        int sel = zb >> 1;
        zb &= 1;
        if (sel) { Ah += selOff; Al += selOff; Bh += selOff; Bl += selOff; C = Calt; }
    }
    const int kc = K / splitk;
    const int kbeg = kchunk * kc;

    Ah += (long long)zb * sA; Al += (long long)zb * sA;
    Bh += (long long)zb * sB; Bl += (long long)zb * sB;
    if (C) C += (long long)zb * sC;
    if (Ch) { Ch += (long long)zb * sC; Cl += (long long)zb * sC; }

    const int brow = blockIdx.y * BM;
    const int bcol = blockIdx.x * BN;
    const int t = threadIdx.x;
    const int lane = t & 31;
    const int wid = t >> 5;
    const int wm = (wid >> 2) * 32;   // 4 warps in m, 32 rows each
    const int wn = (wid & 3) * 32;    // 4 warps in n, 32 cols each
    const int q = lane & 3;
    const int r = lane >> 2;
    const int lg = lane >> 3;      // ldmatrix group 0..3
    const int lr = lane & 7;

    __shared__ __align__(128) char sm[NSTAGE][STAGE_BYTES];
    const uint32_t sm0 = (uint32_t)__cvta_generic_to_shared(&sm[0][0]);

    float acc[2][4][4];
#pragma unroll
    for (int i = 0; i < 2; i++)
#pragma unroll
        for (int j = 0; j < 4; j++)
#pragma unroll
            for (int c = 0; c < 4; c++) acc[i][j][c] = 0.f;

    // cp.async: 512 chunks of 16B per operand per stage, exactly 1/thread each.
    // A (and TB-B): t -> plane = t>>8, m = (t&255)>>1, half = t&1
    // NN-B:         t -> plane = t>>8, k = (t&255)>>4, j = t&15
    const int pl_  = t >> 8;
    const int rem_ = t & 255;
    auto load_stage = [&](int st, int k0) {
        uint32_t base = sm0 + (uint32_t)(st * STAGE_BYTES);
        {
            int m = rem_ >> 1, half = rem_ & 1;
            const bf16* src = (pl_ ? Al : Ah) + (long long)(brow + m) * lda + k0 + half * 8;
            cpa16(base + (uint32_t)(pl_ * 4096 + m * 32 + ((half ^ ((m >> 2) & 1)) * 16)), src);
        }
        if (TB) {
            int n = rem_ >> 1, half = rem_ & 1;
            const bf16* src = (pl_ ? Bl : Bh) + (long long)(bcol + n) * ldb + k0 + half * 8;
            cpa16(base + (uint32_t)(8192 + pl_ * 4096 + n * 32 + ((half ^ ((n >> 2) & 1)) * 16)), src);
        } else {
            int kk = rem_ >> 4, j = rem_ & 15;
            const bf16* src = (pl_ ? Bl : Bh) + (long long)(k0 + kk) * ldb + bcol + j * 8;
            cpa16(base + (uint32_t)(8192 + pl_ * 4096 + kk * 256 + ((j ^ (kk & 7)) * 16)), src);
        }
        cpa_commit();
    };

    const int nIter = kc / BK;
    load_stage(0, kbeg);
    load_stage(1, kbeg + BK);

    for (int it = 0; it < nIter; it++) {
        if (it + 1 < nIter) cpa_wait<1>(); else cpa_wait<0>();
        __syncthreads();
        if (it + 2 < nIter) load_stage((it + 2) % NSTAGE, kbeg + (it + 2) * BK);

        uint32_t base = sm0 + (uint32_t)((it % NSTAGE) * STAGE_BYTES);

        // ---- B fragments (2 planes x 4 nt x 2 regs) ----
        uint32_t Bf[2][4][2];
#pragma unroll
        for (int pl = 0; pl < 2; pl++) {
#pragma unroll
            for (int pair = 0; pair < 2; pair++) {
                int nl = pair * 2, nh = pair * 2 + 1;
                if (TB) {
                    int row = wn + pair * 16 + lr + (lg & 1) * 8;
                    int half = lg >> 1;
                    uint32_t a = base + (uint32_t)(8192 + pl * 4096 + row * 32 +
                                                   ((half ^ ((row >> 2) & 1)) * 16));
                    ldsm_x4(Bf[pl][nl][0], Bf[pl][nh][0], Bf[pl][nl][1], Bf[pl][nh][1], a);
                } else {
                    int krow = lr + (lg & 1) * 8;
                    int j = (wn >> 3) + pair * 2 + (lg >> 1);
                    uint32_t a = base + (uint32_t)(8192 + pl * 4096 + krow * 256 +
                                                   ((j ^ (krow & 7)) * 16));
                    ldsm_x4t(Bf[pl][nl][0], Bf[pl][nl][1], Bf[pl][nh][0], Bf[pl][nh][1], a);
                }
            }
        }

        // ---- A fragments per mt (2), 3 MMA passes ----
#pragma unroll
        for (int mt = 0; mt < 2; mt++) {
            int row = wm + mt * 16 + lr + (lg & 1) * 8;
            int half = lg >> 1;
            uint32_t swz = (uint32_t)((half ^ ((row >> 2) & 1)) * 16);
            uint32_t Ah0, Ah1, Ah2, Ah3, Al0, Al1, Al2, Al3;
            ldsm_x4(Ah0, Ah1, Ah2, Ah3, base + (uint32_t)(row * 32) + swz);
            ldsm_x4(Al0, Al1, Al2, Al3, base + (uint32_t)(4096 + row * 32) + swz);
#pragma unroll
            for (int nt = 0; nt < 4; nt++) {
                mma_bf16(acc[mt][nt], Ah0, Ah1, Ah2, Ah3, Bf[0][nt][0], Bf[0][nt][1]);
                mma_bf16(acc[mt][nt], Ah0, Ah1, Ah2, Ah3, Bf[1][nt][0], Bf[1][nt][1]);
                mma_bf16(acc[mt][nt], Al0, Al1, Al2, Al3, Bf[0][nt][0], Bf[0][nt][1]);
            }
        }
    }

    // ---- epilogue ----
#pragma unroll
    for (int mt = 0; mt < 2; mt++) {
#pragma unroll
        for (int nt = 0; nt < 4; nt++) {
            int row = brow + wm + mt * 16 + r;
            int col = bcol + wn + nt * 8 + 2 * q;
            float b0 = 0.f, b1 = 0.f;
            if (bias && kchunk == 0) { b0 = bias[col]; b1 = bias[col + 1]; }
            float v0 = alpha * acc[mt][nt][0] + b0;
            float v1 = alpha * acc[mt][nt][1] + b1;
            float v2 = alpha * acc[mt][nt][2] + b0;
            float v3 = alpha * acc[mt][nt][3] + b1;
            if (Ch) {
                uint32_t h, l;
                split2(v0, v1, h, l);
                *(uint32_t*)&Ch[(long long)row * ldc + col] = h;
                *(uint32_t*)&Cl[(long long)row * ldc + col] = l;
                split2(v2, v3, h, l);
                *(uint32_t*)&Ch[(long long)(row + 8) * ldc + col] = h;
                *(uint32_t*)&Cl[(long long)(row + 8) * ldc + col] = l;
            } else if (splitk > 1) {
                atomicAdd(&C[(long long)row * ldc + col], v0);
                atomicAdd(&C[(long long)row * ldc + col + 1], v1);
                atomicAdd(&C[(long long)(row + 8) * ldc + col], v2);
                atomicAdd(&C[(long long)(row + 8) * ldc + col + 1], v3);
            } else {
                *(float2*)&C[(long long)row * ldc + col] = make_float2(v0, v1);
                *(float2*)&C[(long long)(row + 8) * ldc + col] = make_float2(v2, v3);
            }
        }
    }
}

// ---------------------------------------------------------------------------
// Elementwise fp32 -> bf16 hi/lo plane split (n4 = count of float4)
// ---------------------------------------------------------------------------
__global__ void split_kernel(const float4* __restrict__ src,
                             uint2* __restrict__ h, uint2* __restrict__ l, int n4)
{
    int i = blockIdx.x * blockDim.x + threadIdx.x;
    if (i < n4) {
        float4 v = src[i];
        uint32_t h0, l0, h1, l1;
        split2(v.x, v.y, h0, l0);
        split2(v.z, v.w, h1, l1);
        h[i] = make_uint2(h0, h1);
        l[i] = make_uint2(l0, l1);
    }
}

// ---------------------------------------------------------------------------
__global__ void lambda_kernel(const float* __restrict__ lq1, const float* __restrict__ lk1,
                              const float* __restrict__ lq2, const float* __restrict__ lk2)
{
    if (threadIdx.x == 0) {
        float d1 = 0.f, d2 = 0.f;
        for (int i = 0; i < 64; i++) {
            d1 += lq1[i] * lk1[i];
            d2 += lq2[i] * lk2[i];
        }
        g_lambda = expf(d1) - expf(d2) + (0.8f - 0.6f * expf(-0.3f * 0.0f));
    }
}

// cvec[n] = bo[n] + (1-lam) * sum_k bv[k]*Wo[k,n]; one block per n.
__global__ __launch_bounds__(256) void cvec_kernel(
    const float* __restrict__ bv, const float* __restrict__ Wo,
    const float* __restrict__ bo)
{
    const int n = blockIdx.x;
    const int t = threadIdx.x;
    float s = 0.f;
    for (int k = t; k < 8192; k += 256)
        s += bv[k] * Wo[(long long)k * 512 + n];
    __shared__ float red[256];
    red[t] = s;
    __syncthreads();
    for (int o = 128; o; o >>= 1) {
        if (t < o) red[t] += red[t + o];
        __syncthreads();
    }
    if (t == 0) g_cvec[n] = bo[n] + (1.f - g_lambda) * red[0];
}

// ---------------------------------------------------------------------------
// Fused dual softmax + differential combine; writes bf16 hi/lo planes.
// One block per row (2048 cols); thread t owns cols [8t, 8t+8).
// ---------------------------------------------------------------------------
__global__ __launch_bounds__(256) void softmax_diff_kernel(
    const float* __restrict__ l1, const float* __restrict__ l2,
    bf16* __restrict__ dh, bf16* __restrict__ dl)
{
    long long row = blockIdx.x;
    const float* r1 = l1 + row * 2048;
    const float* r2 = l2 + row * 2048;
    const int t = threadIdx.x;
    const int lane = t & 31, warp = t >> 5;

    float v1[8], v2[8];
    *(float4*)&v1[0] = *(const float4*)&r1[t * 8];
    *(float4*)&v1[4] = *(const float4*)&r1[t * 8 + 4];
    *(float4*)&v2[0] = *(const float4*)&r2[t * 8];
    *(float4*)&v2[4] = *(const float4*)&r2[t * 8 + 4];

    float m1 = -1e30f, m2 = -1e30f;
#pragma unroll
    for (int i = 0; i < 8; i++) {
        m1 = fmaxf(m1, v1[i]);
        m2 = fmaxf(m2, v2[i]);
    }
#pragma unroll
    for (int o = 16; o; o >>= 1) {
        m1 = fmaxf(m1, __shfl_xor_sync(0xffffffffu, m1, o));
        m2 = fmaxf(m2, __shfl_xor_sync(0xffffffffu, m2, o));
    }
    __shared__ float s1[8], s2[8];
    if (lane == 0) { s1[warp] = m1; s2[warp] = m2; }
    __syncthreads();
    m1 = s1[0]; m2 = s2[0];
#pragma unroll
    for (int w = 1; w < 8; w++) {
        m1 = fmaxf(m1, s1[w]);
        m2 = fmaxf(m2, s2[w]);
    }

    float e1[8], e2[8];
    float sum1 = 0.f, sum2 = 0.f;
#pragma unroll
    for (int i = 0; i < 8; i++) {
        e1[i] = __expf(v1[i] - m1);
        e2[i] = __expf(v2[i] - m2);
        sum1 += e1[i];
        sum2 += e2[i];
    }
#pragma unroll
    for (int o = 16; o; o >>= 1) {
        sum1 += __shfl_xor_sync(0xffffffffu, sum1, o);
        sum2 += __shfl_xor_sync(0xffffffffu, sum2, o);
    }
    __syncthreads();
    if (lane == 0) { s1[warp] = sum1; s2[warp] = sum2; }
    __syncthreads();
    sum1 = 0.f; sum2 = 0.f;
#pragma unroll
    for (int w = 0; w < 8; w++) { sum1 += s1[w]; sum2 += s2[w]; }

    const float inv1 = 1.f / sum1;
    const float inv2 = g_lambda / sum2;
    uint4 hv, lv;
    float d0, d1v;
    d0 = e1[0] * inv1 - e2[0] * inv2; d1v = e1[1] * inv1 - e2[1] * inv2;
    split2(d0, d1v, hv.x, lv.x);
    d0 = e1[2] * inv1 - e2[2] * inv2; d1v = e1[3] * inv1 - e2[3] * inv2;
    split2(d0, d1v, hv.y, lv.y);
    d0 = e1[4] * inv1 - e2[4] * inv2; d1v = e1[5] * inv1 - e2[5] * inv2;
    split2(d0, d1v, hv.z, lv.z);
    d0 = e1[6] * inv1 - e2[6] * inv2; d1v = e1[7] * inv1 - e2[7] * inv2;
    split2(d0, d1v, hv.w, lv.w);
    *(uint4*)&dh[row * 2048 + t * 8] = hv;
    *(uint4*)&dl[row * 2048 + t * 8] = lv;
}

// ---------------------------------------------------------------------------
extern "C" void kernel_launch(void* const* d_in, const int* in_sizes, int n_in,
                              void* d_out, int out_size)
{
    const float* x    = (const float*)d_in[0];
    const float* Wqkv = (const float*)d_in[1];
    const float* bqkv = (const float*)d_in[2];
    const float* Wv   = (const float*)d_in[3];
    const float* bv   = (const float*)d_in[4];
    const float* Wo   = (const float*)d_in[5];
    const float* bo   = (const float*)d_in[6];
    const float* lq1  = (const float*)d_in[7];
    const float* lk1  = (const float*)d_in[8];
    const float* lq2  = (const float*)d_in[9];
    const float* lk2  = (const float*)d_in[10];
    float* out = (float*)d_out;

    float *Mm, *l1, *l2, *cvec;
    bf16 *xh, *xl, *wqh, *wql, *wvh, *wvl, *woh, *wol;
    bf16 *qh, *ql, *mh, *ml, *vph, *vpl, *dh, *dl;
    cudaGetSymbolAddress((void**)&Mm,  g_M);
    cudaGetSymbolAddress((void**)&l1,  g_l1);
    cudaGetSymbolAddress((void**)&l2,  g_l2);
    cudaGetSymbolAddress((void**)&cvec, g_cvec);
    cudaGetSymbolAddress((void**)&xh,  g_xh);   cudaGetSymbolAddress((void**)&xl,  g_xl);
    cudaGetSymbolAddress((void**)&wqh, g_wqh);  cudaGetSymbolAddress((void**)&wql, g_wql);
    cudaGetSymbolAddress((void**)&wvh, g_wvh);  cudaGetSymbolAddress((void**)&wvl, g_wvl);
    cudaGetSymbolAddress((void**)&woh, g_woh);  cudaGetSymbolAddress((void**)&wol, g_wol);
    cudaGetSymbolAddress((void**)&qh,  g_qh);   cudaGetSymbolAddress((void**)&ql,  g_ql);
    cudaGetSymbolAddress((void**)&mh,  g_mh);   cudaGetSymbolAddress((void**)&ml,  g_ml);
    cudaGetSymbolAddress((void**)&vph, g_vph);  cudaGetSymbolAddress((void**)&vpl, g_vpl);
    cudaGetSymbolAddress((void**)&dh,  g_dh);   cudaGetSymbolAddress((void**)&dl,  g_dl);

    const long long SQ  = 2048LL * 1024;   // qkv plane batch stride
    const long long SL  = 2048LL * 2048;   // logits / diff batch stride
    const long long SV  = 2048LL * 512;    // V' / out batch stride

    // 0) scalars + input splits
    lambda_kernel<<<1, 32>>>(lq1, lk1, lq2, lk2);
    cvec_kernel<<<512, 256>>>(bv, Wo, bo);
    split_kernel<<<2048, 256>>>((const float4*)x,    (uint2*)xh,  (uint2*)xl,  4096 * 512 / 4);
    split_kernel<<<512,  256>>>((const float4*)Wqkv, (uint2*)wqh, (uint2*)wql, 512 * 1024 / 4);
    split_kernel<<<4096, 256>>>((const float4*)Wv,   (uint2*)wvh, (uint2*)wvl, 512 * 8192 / 4);
    split_kernel<<<4096, 256>>>((const float4*)Wo,   (uint2*)woh, (uint2*)wol, 8192 * 512 / 4);

    // 1) qkv = x @ Wqkv + bqkv -> planes  [4096,1024]
    bf_gemm<false><<<dim3(8, 32, 1), NTH>>>(
        xh, xl, wqh, wql, nullptr, nullptr, qh, ql,
        512, 512, 1024, 1024, 0, 0, 0, 1.f, bqkv, 1, 0);

    // 2) M = Wv @ Wo  (fp32, splitK=16), then split to planes
    cudaMemsetAsync(Mm, 0, 512 * 512 * sizeof(float));
    bf_gemm<false><<<dim3(4, 4, 16), NTH>>>(
        wvh, wvl, woh, wol, Mm, nullptr, nullptr, nullptr,
        8192, 8192, 512, 512, 0, 0, 0, 1.f, nullptr, 16, 0);
    split_kernel<<<256, 256>>>((const float4*)Mm, (uint2*)mh, (uint2*)ml, 512 * 512 / 4);

    // 3) V' = x @ M -> planes  [4096,512]
    bf_gemm<false><<<dim3(4, 32, 1), NTH>>>(
        xh, xl, mh, ml, nullptr, nullptr, vph, vpl,
        512, 512, 512, 512, 0, 0, 0, 1.f, nullptr, 1, 0);

    // 4) logits merged (z=0,1 -> l1 via Q1/K1; z=2,3 -> l2 via +256 offset)
    bf_gemm<true><<<dim3(16, 16, 4), NTH>>>(
        qh + 0, ql + 0, qh + 512, ql + 512, l1, l2, nullptr, nullptr,
        256, 1024, 1024, 2048, SQ, SQ, SL, 0.125f, nullptr, 1, 256);

    // 5) diff = softmax(l1) - lam*softmax(l2) -> planes
    softmax_diff_kernel<<<4096, 256>>>(l1, l2, dh, dl);

    // 6) out = diff @ V' + cvec  (fp32, splitK=2)
    cudaMemsetAsync(out, 0, 2 * 2048 * 512 * sizeof(float));
    bf_gemm<false><<<dim3(4, 16, 4), NTH>>>(
        dh, dl, vph, vpl, out, nullptr, nullptr, nullptr,
        2048, 2048, 512, 512, SL, SV, SV, 1.f, cvec, 2, 0);
}

// round 12
// speedup vs baseline: 5.4110x; 1.0122x over previous
#include <cuda_runtime.h>
#include <cuda_bf16.h>
#include <math.h>
#include <stdint.h>

// ---------------------------------------------------------------------------
// DifferentialAttention, folded algebra, 3-pass bf16 (hi/lo plane) GEMMs.
// R12: BK=32 stages (two 16-K sub-tiles per barrier) with 96KB dynamic smem
// to halve barrier count and de-phase-lock ldmatrix/MMA bursts. tcgen05 is
// unavailable (harness targets sm_100 without 'a'); legacy mma.sync path.
//   qkv  = x @ Wqkv + bqkv          -> planes      [4096,1024]
//   M    = Wv @ Wo                  -> fp32 (splitK=16) -> planes [512,512]
//   V'   = x @ M                    -> planes      [4096,512]
//   l1/l2 = Q@K^T * 0.125           -> fp32 (merged z=4)
//   diff = softmax(l1)-lam*softmax(l2) -> planes   [2][2048,2048]
//   out  = diff @ V' + cvec         -> fp32 (splitK=2)
// ---------------------------------------------------------------------------

#define BM 128
#define BN 128
#define BKS 32              // K per stage (two 16-K sub-tiles)
#define NTH 512
#define NSTAGE 3
#define SUB_BYTES 16384     // one 16-K sub-tile: A 2x4KB + B 2x4KB
#define STAGE_BYTES 32768
#define DSMEM_BYTES (NSTAGE * STAGE_BYTES)   // 98304

typedef __nv_bfloat16 bf16;

// fp32 scratch
__device__ float g_M[512 * 512];
__device__ float g_l1[2 * 2048 * 2048];
__device__ float g_l2[2 * 2048 * 2048];
__device__ float g_lambda;
__device__ float g_cvec[512];
// bf16 hi/lo planes
__device__ bf16 g_xh[4096 * 512],  g_xl[4096 * 512];
__device__ bf16 g_wqh[512 * 1024], g_wql[512 * 1024];
__device__ bf16 g_wvh[512 * 8192], g_wvl[512 * 8192];
__device__ bf16 g_woh[8192 * 512], g_wol[8192 * 512];
__device__ bf16 g_qh[4096 * 1024], g_ql[4096 * 1024];
__device__ bf16 g_mh[512 * 512],   g_ml[512 * 512];
__device__ bf16 g_vph[4096 * 512], g_vpl[4096 * 512];
__device__ bf16 g_dh[2 * 2048 * 2048], g_dl[2 * 2048 * 2048];

// split two fp32 (x = even idx, y = odd idx) into packed bf16x2 hi and lo
__device__ __forceinline__ void split2(float x, float y, uint32_t& h, uint32_t& l) {
    asm("cvt.rn.bf16x2.f32 %0, %1, %2;" : "=r"(h) : "f"(y), "f"(x));
    float hx = __uint_as_float(h << 16);
    float hy = __uint_as_float(h & 0xffff0000u);
    asm("cvt.rn.bf16x2.f32 %0, %1, %2;" : "=r"(l) : "f"(y - hy), "f"(x - hx));
}

__device__ __forceinline__ void mma_bf16(float c[4],
                                         uint32_t a0, uint32_t a1, uint32_t a2, uint32_t a3,
                                         uint32_t b0, uint32_t b1) {
    asm volatile(
        "mma.sync.aligned.m16n8k16.row.col.f32.bf16.bf16.f32 "
        "{%0,%1,%2,%3}, {%4,%5,%6,%7}, {%8,%9}, {%0,%1,%2,%3};"
        : "+f"(c[0]), "+f"(c[1]), "+f"(c[2]), "+f"(c[3])
        : "r"(a0), "r"(a1), "r"(a2), "r"(a3), "r"(b0), "r"(b1));
}

__device__ __forceinline__ void ldsm_x4(uint32_t& r0, uint32_t& r1, uint32_t& r2, uint32_t& r3,
                                        uint32_t addr) {
    asm volatile("ldmatrix.sync.aligned.m8n8.x4.shared.b16 {%0,%1,%2,%3}, [%4];"
                 : "=r"(r0), "=r"(r1), "=r"(r2), "=r"(r3) : "r"(addr));
}
__device__ __forceinline__ void ldsm_x4t(uint32_t& r0, uint32_t& r1, uint32_t& r2, uint32_t& r3,
                                         uint32_t addr) {
    asm volatile("ldmatrix.sync.aligned.m8n8.x4.trans.shared.b16 {%0,%1,%2,%3}, [%4];"
                 : "=r"(r0), "=r"(r1), "=r"(r2), "=r"(r3) : "r"(addr));
}

__device__ __forceinline__ void cpa16(uint32_t smem, const void* gmem) {
    asm volatile("cp.async.ca.shared.global [%0], [%1], 16;" :: "r"(smem), "l"(gmem));
}
__device__ __forceinline__ void cpa_commit() { asm volatile("cp.async.commit_group;"); }
template <int N>
__device__ __forceinline__ void cpa_wait() { asm volatile("cp.async.wait_group %0;" :: "n"(N)); }

// ---------------------------------------------------------------------------
// 3-pass bf16 GEMM over hi/lo planes. 512 threads, 16 warps (4x4 of 32x32).
// BKS=32 stages: two 16-K sub-tiles, one __syncthreads per stage.
// Output: Ch!=null -> bf16 plane store (splitk=1); else splitk>1 -> fp32
// atomicAdd; else fp32 store. Calt: merged logits (z in [2,4) -> +selOff).
// Sub-tile layout (16KB): A at +0 (plane*4096 + m*32 + swz16);
//                         B at +8192 (TB same as A; NN plane*4096 + k*256 + swz16).
// ---------------------------------------------------------------------------
template <bool TB>
__global__ __launch_bounds__(NTH, 1) void bf_gemm(
    const bf16* __restrict__ Ah, const bf16* __restrict__ Al,
    const bf16* __restrict__ Bh, const bf16* __restrict__ Bl,
    float* __restrict__ C, float* __restrict__ Calt,
    bf16* __restrict__ Ch, bf16* __restrict__ Cl,
    int K, int lda, int ldb, int ldc,
    long long sA, long long sB, long long sC,
    float alpha, const float* __restrict__ bias, int splitk, int selOff)
{
    int zb = blockIdx.z / splitk;
    const int kchunk = blockIdx.z % splitk;
    if (Calt) {
        int sel = zb >> 1;
        zb &= 1;
        if (sel) { Ah += selOff; Al += selOff; Bh += selOff; Bl += selOff; C = Calt; }
    }
    const int kc = K / splitk;
    const int kbeg = kchunk * kc;

    Ah += (long long)zb * sA; Al += (long long)zb * sA;
    Bh += (long long)zb * sB; Bl += (long long)zb * sB;
    if (C) C += (long long)zb * sC;
    if (Ch) { Ch += (long long)zb * sC; Cl += (long long)zb * sC; }

    const int brow = blockIdx.y * BM;
    const int bcol = blockIdx.x * BN;
    const int t = threadIdx.x;
    const int lane = t & 31;
    const int wid = t >> 5;
    const int wm = (wid >> 2) * 32;   // 4 warps in m, 32 rows each
    const int wn = (wid & 3) * 32;    // 4 warps in n, 32 cols each
    const int q = lane & 3;
    const int r = lane >> 2;
    const int lg = lane >> 3;      // ldmatrix group 0..3
    const int lr = lane & 7;

    extern __shared__ __align__(128) char sm[];
    const uint32_t sm0 = (uint32_t)__cvta_generic_to_shared(sm);

    float acc[2][4][4];
#pragma unroll
    for (int i = 0; i < 2; i++)
#pragma unroll
        for (int j = 0; j < 4; j++)
#pragma unroll
            for (int c = 0; c < 4; c++) acc[i][j][c] = 0.f;

    // cp.async: per sub-tile, 512 16B-chunks per operand, 1/thread each.
    // A (and TB-B): t -> plane = t>>8, m = (t&255)>>1, half = t&1
    // NN-B:         t -> plane = t>>8, k = (t&255)>>4, j = t&15
    const int pl_  = t >> 8;
    const int rem_ = t & 255;
    auto load_stage = [&](int st, int k0) {
        uint32_t sbase = sm0 + (uint32_t)(st * STAGE_BYTES);
#pragma unroll
        for (int sub = 0; sub < 2; sub++) {
            uint32_t base = sbase + (uint32_t)(sub * SUB_BYTES);
            int ks = k0 + sub * 16;
            {
                int m = rem_ >> 1, half = rem_ & 1;
                const bf16* src = (pl_ ? Al : Ah) + (long long)(brow + m) * lda + ks + half * 8;
                cpa16(base + (uint32_t)(pl_ * 4096 + m * 32 + ((half ^ ((m >> 2) & 1)) * 16)), src);
            }
            if (TB) {
                int n = rem_ >> 1, half = rem_ & 1;
                const bf16* src = (pl_ ? Bl : Bh) + (long long)(bcol + n) * ldb + ks + half * 8;
                cpa16(base + (uint32_t)(8192 + pl_ * 4096 + n * 32 + ((half ^ ((n >> 2) & 1)) * 16)), src);
            } else {
                int kk = rem_ >> 4, j = rem_ & 15;
                const bf16* src = (pl_ ? Bl : Bh) + (long long)(ks + kk) * ldb + bcol + j * 8;
                cpa16(base + (uint32_t)(8192 + pl_ * 4096 + kk * 256 + ((j ^ (kk & 7)) * 16)), src);
            }
        }
        cpa_commit();
    };

    // compute one 16-K sub-tile at smem offset `base`
    auto compute_sub = [&](uint32_t base) {
        uint32_t Bf[2][4][2];
#pragma unroll
        for (int pl = 0; pl < 2; pl++) {
#pragma unroll
            for (int pair = 0; pair < 2; pair++) {
                int nl = pair * 2, nh = pair * 2 + 1;
                if (TB) {
                    int row = wn + pair * 16 + lr + (lg & 1) * 8;
                    int half = lg >> 1;
                    uint32_t a = base + (uint32_t)(8192 + pl * 4096 + row * 32 +
                                                   ((half ^ ((row >> 2) & 1)) * 16));
                    ldsm_x4(Bf[pl][nl][0], Bf[pl][nh][0], Bf[pl][nl][1], Bf[pl][nh][1], a);
                } else {
                    int krow = lr + (lg & 1) * 8;
                    int j = (wn >> 3) + pair * 2 + (lg >> 1);
                    uint32_t a = base + (uint32_t)(8192 + pl * 4096 + krow * 256 +
                                                   ((j ^ (krow & 7)) * 16));
                    ldsm_x4t(Bf[pl][nl][0], Bf[pl][nl][1], Bf[pl][nh][0], Bf[pl][nh][1], a);
                }
            }
        }
#pragma unroll
        for (int mt = 0; mt < 2; mt++) {
            int row = wm + mt * 16 + lr + (lg & 1) * 8;
            int half = lg >> 1;
            uint32_t swz = (uint32_t)((half ^ ((row >> 2) & 1)) * 16);
            uint32_t Ah0, Ah1, Ah2, Ah3, Al0, Al1, Al2, Al3;
            ldsm_x4(Ah0, Ah1, Ah2, Ah3, base + (uint32_t)(row * 32) + swz);
            ldsm_x4(Al0, Al1, Al2, Al3, base + (uint32_t)(4096 + row * 32) + swz);
#pragma unroll
            for (int nt = 0; nt < 4; nt++) {
                mma_bf16(acc[mt][nt], Ah0, Ah1, Ah2, Ah3, Bf[0][nt][0], Bf[0][nt][1]);
                mma_bf16(acc[mt][nt], Ah0, Ah1, Ah2, Ah3, Bf[1][nt][0], Bf[1][nt][1]);
                mma_bf16(acc[mt][nt], Al0, Al1, Al2, Al3, Bf[0][nt][0], Bf[0][nt][1]);
            }
        }
    };

    const int nIter = kc / BKS;
    load_stage(0, kbeg);
    if (nIter > 1) load_stage(1, kbeg + BKS);

    for (int it = 0; it < nIter; it++) {
        if (it + 1 < nIter) cpa_wait<1>(); else cpa_wait<0>();
        __syncthreads();
        if (it + 2 < nIter) load_stage((it + 2) % NSTAGE, kbeg + (it + 2) * BKS);

        uint32_t sbase = sm0 + (uint32_t)((it % NSTAGE) * STAGE_BYTES);
        compute_sub(sbase);
        compute_sub(sbase + SUB_BYTES);
        __syncthreads();
    }

    // ---- epilogue ----
#pragma unroll
    for (int mt = 0; mt < 2; mt++) {
#pragma unroll
        for (int nt = 0; nt < 4; nt++) {
            int row = brow + wm + mt * 16 + r;
            int col = bcol + wn + nt * 8 + 2 * q;
            float b0 = 0.f, b1 = 0.f;
            if (bias && kchunk == 0) { b0 = bias[col]; b1 = bias[col + 1]; }
            float v0 = alpha * acc[mt][nt][0] + b0;
            float v1 = alpha * acc[mt][nt][1] + b1;
            float v2 = alpha * acc[mt][nt][2] + b0;
            float v3 = alpha * acc[mt][nt][3] + b1;
            if (Ch) {
                uint32_t h, l;
                split2(v0, v1, h, l);
                *(uint32_t*)&Ch[(long long)row * ldc + col] = h;
                *(uint32_t*)&Cl[(long long)row * ldc + col] = l;
                split2(v2, v3, h, l);
                *(uint32_t*)&Ch[(long long)(row + 8) * ldc + col] = h;
                *(uint32_t*)&Cl[(long long)(row + 8) * ldc + col] = l;
            } else if (splitk > 1) {
                atomicAdd(&C[(long long)row * ldc + col], v0);
                atomicAdd(&C[(long long)row * ldc + col + 1], v1);
                atomicAdd(&C[(long long)(row + 8) * ldc + col], v2);
                atomicAdd(&C[(long long)(row + 8) * ldc + col + 1], v3);
            } else {
                *(float2*)&C[(long long)row * ldc + col] = make_float2(v0, v1);
                *(float2*)&C[(long long)(row + 8) * ldc + col] = make_float2(v2, v3);
            }
        }
    }
}

// ---------------------------------------------------------------------------
__global__ void split_kernel(const float4* __restrict__ src,
                             uint2* __restrict__ h, uint2* __restrict__ l, int n4)
{
    int i = blockIdx.x * blockDim.x + threadIdx.x;
    if (i < n4) {
        float4 v = src[i];
        uint32_t h0, l0, h1, l1;
        split2(v.x, v.y, h0, l0);
        split2(v.z, v.w, h1, l1);
        h[i] = make_uint2(h0, h1);
        l[i] = make_uint2(l0, l1);
    }
}

__global__ void lambda_kernel(const float* __restrict__ lq1, const float* __restrict__ lk1,
                              const float* __restrict__ lq2, const float* __restrict__ lk2)
{
    if (threadIdx.x == 0) {
        float d1 = 0.f, d2 = 0.f;
        for (int i = 0; i < 64; i++) {
            d1 += lq1[i] * lk1[i];
            d2 += lq2[i] * lk2[i];
        }
        g_lambda = expf(d1) - expf(d2) + (0.8f - 0.6f * expf(-0.3f * 0.0f));
    }
}

// cvec[n] = bo[n] + (1-lam) * sum_k bv[k]*Wo[k,n]; one block per n.
__global__ __launch_bounds__(256) void cvec_kernel(
    const float* __restrict__ bv, const float* __restrict__ Wo,
    const float* __restrict__ bo)
{
    const int n = blockIdx.x;
    const int t = threadIdx.x;
    float s = 0.f;
    for (int k = t; k < 8192; k += 256)
        s += bv[k] * Wo[(long long)k * 512 + n];
    __shared__ float red[256];
    red[t] = s;
    __syncthreads();
    for (int o = 128; o; o >>= 1) {
        if (t < o) red[t] += red[t + o];
        __syncthreads();
    }
    if (t == 0) g_cvec[n] = bo[n] + (1.f - g_lambda) * red[0];
}

// ---------------------------------------------------------------------------
// Fused dual softmax + differential combine; writes bf16 hi/lo planes.
// ---------------------------------------------------------------------------
__global__ __launch_bounds__(256) void softmax_diff_kernel(
    const float* __restrict__ l1, const float* __restrict__ l2,
    bf16* __restrict__ dh, bf16* __restrict__ dl)
{
    long long row = blockIdx.x;
    const float* r1 = l1 + row * 2048;
    const float* r2 = l2 + row * 2048;
    const int t = threadIdx.x;
    const int lane = t & 31, warp = t >> 5;

    float v1[8], v2[8];
    *(float4*)&v1[0] = *(const float4*)&r1[t * 8];
    *(float4*)&v1[4] = *(const float4*)&r1[t * 8 + 4];
    *(float4*)&v2[0] = *(const float4*)&r2[t * 8];
    *(float4*)&v2[4] = *(const float4*)&r2[t * 8 + 4];

    float m1 = -1e30f, m2 = -1e30f;
#pragma unroll
    for (int i = 0; i < 8; i++) {
        m1 = fmaxf(m1, v1[i]);
        m2 = fmaxf(m2, v2[i]);
    }
#pragma unroll
    for (int o = 16; o; o >>= 1) {
        m1 = fmaxf(m1, __shfl_xor_sync(0xffffffffu, m1, o));
        m2 = fmaxf(m2, __shfl_xor_sync(0xffffffffu, m2, o));
    }
    __shared__ float s1[8], s2[8];
    if (lane == 0) { s1[warp] = m1; s2[warp] = m2; }
    __syncthreads();
    m1 = s1[0]; m2 = s2[0];
#pragma unroll
    for (int w = 1; w < 8; w++) {
        m1 = fmaxf(m1, s1[w]);
        m2 = fmaxf(m2, s2[w]);
    }

    float e1[8], e2[8];
    float sum1 = 0.f, sum2 = 0.f;
#pragma unroll
    for (int i = 0; i < 8; i++) {
        e1[i] = __expf(v1[i] - m1);
        e2[i] = __expf(v2[i] - m2);
        sum1 += e1[i];
        sum2 += e2[i];
    }
#pragma unroll
    for (int o = 16; o; o >>= 1) {
        sum1 += __shfl_xor_sync(0xffffffffu, sum1, o);
        sum2 += __shfl_xor_sync(0xffffffffu, sum2, o);
    }
    __syncthreads();
    if (lane == 0) { s1[warp] = sum1; s2[warp] = sum2; }
    __syncthreads();
    sum1 = 0.f; sum2 = 0.f;
#pragma unroll
    for (int w = 0; w < 8; w++) { sum1 += s1[w]; sum2 += s2[w]; }

    const float inv1 = 1.f / sum1;
    const float inv2 = g_lambda / sum2;
    uint4 hv, lv;
    float d0, d1v;
    d0 = e1[0] * inv1 - e2[0] * inv2; d1v = e1[1] * inv1 - e2[1] * inv2;
    split2(d0, d1v, hv.x, lv.x);
    d0 = e1[2] * inv1 - e2[2] * inv2; d1v = e1[3] * inv1 - e2[3] * inv2;
    split2(d0, d1v, hv.y, lv.y);
    d0 = e1[4] * inv1 - e2[4] * inv2; d1v = e1[5] * inv1 - e2[5] * inv2;
    split2(d0, d1v, hv.z, lv.z);
    d0 = e1[6] * inv1 - e2[6] * inv2; d1v = e1[7] * inv1 - e2[7] * inv2;
    split2(d0, d1v, hv.w, lv.w);
    *(uint4*)&dh[row * 2048 + t * 8] = hv;
    *(uint4*)&dl[row * 2048 + t * 8] = lv;
}

// ---------------------------------------------------------------------------
extern "C" void kernel_launch(void* const* d_in, const int* in_sizes, int n_in,
                              void* d_out, int out_size)
{
    const float* x    = (const float*)d_in[0];
    const float* Wqkv = (const float*)d_in[1];
    const float* bqkv = (const float*)d_in[2];
    const float* Wv   = (const float*)d_in[3];
    const float* bv   = (const float*)d_in[4];
    const float* Wo   = (const float*)d_in[5];
    const float* bo   = (const float*)d_in[6];
    const float* lq1  = (const float*)d_in[7];
    const float* lk1  = (const float*)d_in[8];
    const float* lq2  = (const float*)d_in[9];
    const float* lk2  = (const float*)d_in[10];
    float* out = (float*)d_out;

    cudaFuncSetAttribute(bf_gemm<false>, cudaFuncAttributeMaxDynamicSharedMemorySize, DSMEM_BYTES);
    cudaFuncSetAttribute(bf_gemm<true>,  cudaFuncAttributeMaxDynamicSharedMemorySize, DSMEM_BYTES);

    float *Mm, *l1, *l2, *cvec;
    bf16 *xh, *xl, *wqh, *wql, *wvh, *wvl, *woh, *wol;
    bf16 *qh, *ql, *mh, *ml, *vph, *vpl, *dh, *dl;
    cudaGetSymbolAddress((void**)&Mm,  g_M);
    cudaGetSymbolAddress((void**)&l1,  g_l1);
    cudaGetSymbolAddress((void**)&l2,  g_l2);
    cudaGetSymbolAddress((void**)&cvec, g_cvec);
    cudaGetSymbolAddress((void**)&xh,  g_xh);   cudaGetSymbolAddress((void**)&xl,  g_xl);
    cudaGetSymbolAddress((void**)&wqh, g_wqh);  cudaGetSymbolAddress((void**)&wql, g_wql);
    cudaGetSymbolAddress((void**)&wvh, g_wvh);  cudaGetSymbolAddress((void**)&wvl, g_wvl);
    cudaGetSymbolAddress((void**)&woh, g_woh);  cudaGetSymbolAddress((void**)&wol, g_wol);
    cudaGetSymbolAddress((void**)&qh,  g_qh);   cudaGetSymbolAddress((void**)&ql,  g_ql);
    cudaGetSymbolAddress((void**)&mh,  g_mh);   cudaGetSymbolAddress((void**)&ml,  g_ml);
    cudaGetSymbolAddress((void**)&vph, g_vph);  cudaGetSymbolAddress((void**)&vpl, g_vpl);
    cudaGetSymbolAddress((void**)&dh,  g_dh);   cudaGetSymbolAddress((void**)&dl,  g_dl);

    const long long SQ  = 2048LL * 1024;   // qkv plane batch stride
    const long long SL  = 2048LL * 2048;   // logits / diff batch stride
    const long long SV  = 2048LL * 512;    // V' / out batch stride

    // 0) scalars + input splits
    lambda_kernel<<<1, 32>>>(lq1, lk1, lq2, lk2);
    cvec_kernel<<<512, 256>>>(bv, Wo, bo);
    split_kernel<<<2048, 256>>>((const float4*)x,    (uint2*)xh,  (uint2*)xl,  4096 * 512 / 4);
    split_kernel<<<512,  256>>>((const float4*)Wqkv, (uint2*)wqh, (uint2*)wql, 512 * 1024 / 4);
    split_kernel<<<4096, 256>>>((const float4*)Wv,   (uint2*)wvh, (uint2*)wvl, 512 * 8192 / 4);
    split_kernel<<<4096, 256>>>((const float4*)Wo,   (uint2*)woh, (uint2*)wol, 8192 * 512 / 4);

    // 1) qkv = x @ Wqkv + bqkv -> planes  [4096,1024]
    bf_gemm<false><<<dim3(8, 32, 1), NTH, DSMEM_BYTES>>>(
        xh, xl, wqh, wql, nullptr, nullptr, qh, ql,
        512, 512, 1024, 1024, 0, 0, 0, 1.f, bqkv, 1, 0);

    // 2) M = Wv @ Wo  (fp32, splitK=16), then split to planes
    cudaMemsetAsync(Mm, 0, 512 * 512 * sizeof(float));
    bf_gemm<false><<<dim3(4, 4, 16), NTH, DSMEM_BYTES>>>(
        wvh, wvl, woh, wol, Mm, nullptr, nullptr, nullptr,
        8192, 8192, 512, 512, 0, 0, 0, 1.f, nullptr, 16, 0);
    split_kernel<<<256, 256>>>((const float4*)Mm, (uint2*)mh, (uint2*)ml, 512 * 512 / 4);

    // 3) V' = x @ M -> planes  [4096,512]
    bf_gemm<false><<<dim3(4, 32, 1), NTH, DSMEM_BYTES>>>(
        xh, xl, mh, ml, nullptr, nullptr, vph, vpl,
        512, 512, 512, 512, 0, 0, 0, 1.f, nullptr, 1, 0);

    // 4) logits merged (z=0,1 -> l1 via Q1/K1; z=2,3 -> l2 via +256 offset)
    bf_gemm<true><<<dim3(16, 16, 4), NTH, DSMEM_BYTES>>>(
        qh + 0, ql + 0, qh + 512, ql + 512, l1, l2, nullptr, nullptr,
        256, 1024, 1024, 2048, SQ, SQ, SL, 0.125f, nullptr, 1, 256);

    // 5) diff = softmax(l1) - lam*softmax(l2) -> planes
    softmax_diff_kernel<<<4096, 256>>>(l1, l2, dh, dl);

    // 6) out = diff @ V' + cvec  (fp32, splitK=2)
    cudaMemsetAsync(out, 0, 2 * 2048 * 512 * sizeof(float));
    bf_gemm<false><<<dim3(4, 16, 4), NTH, DSMEM_BYTES>>>(
        dh, dl, vph, vpl, out, nullptr, nullptr, nullptr,
        2048, 2048, 512, 512, SL, SV, SV, 1.f, cvec, 2, 0);
}

// round 13
// speedup vs baseline: 6.1501x; 1.1366x over previous
#include <cuda_runtime.h>
#include <cuda_fp16.h>
#include <math.h>
#include <stdint.h>

// ---------------------------------------------------------------------------
// DifferentialAttention, folded algebra, fp16 hi/lo plane GEMMs.
// R13: fp16 planes (2^-22 3-pass error); final GEMM demoted to plain 1-pass
// fp16 (single-plane diff and V'), splitK=4; launch order tuned so ncu -s 5
// profiles the qkv GEMM.
//   qkv  = x @ Wqkv + bqkv          -> planes      [4096,1024]   (3-pass)
//   M    = Wv @ Wo                  -> fp32 (splitK=16) -> planes (3-pass)
//   V'   = x @ M                    -> single fp16 plane          (3-pass)
//   l1/l2 = Q@K^T * 0.125           -> fp32 (merged z=4)          (3-pass)
//   diff = softmax(l1)-lam*softmax(l2) -> single fp16 plane
//   out  = diff @ V' + cvec         -> fp32 (splitK=4)            (1-pass)
// ---------------------------------------------------------------------------

#define BM 128
#define BN 128
#define BKS 32              // K per stage (two 16-K sub-tiles)
#define NTH 512
#define NSTAGE 3
#define SUB_BYTES 16384
#define STAGE_BYTES 32768
#define DSMEM_BYTES (NSTAGE * STAGE_BYTES)   // 98304

typedef __half fp16;

// fp32 scratch
__device__ float g_M[512 * 512];
__device__ float g_l1[2 * 2048 * 2048];
__device__ float g_l2[2 * 2048 * 2048];
__device__ float g_lambda;
__device__ float g_cvec[512];
// fp16 hi/lo planes
__device__ fp16 g_xh[4096 * 512],  g_xl[4096 * 512];
__device__ fp16 g_wqh[512 * 1024], g_wql[512 * 1024];
__device__ fp16 g_wvh[512 * 8192], g_wvl[512 * 8192];
__device__ fp16 g_woh[8192 * 512], g_wol[8192 * 512];
__device__ fp16 g_qh[4096 * 1024], g_ql[4096 * 1024];
__device__ fp16 g_mh[512 * 512],   g_ml[512 * 512];
__device__ fp16 g_vph[4096 * 512];                 // single plane (feeds 1-pass final)
__device__ fp16 g_dh[2 * 2048 * 2048];             // single plane diff

// split two fp32 (x = even idx, y = odd idx) into packed fp16x2 hi and lo
__device__ __forceinline__ void split2(float x, float y, uint32_t& h, uint32_t& l) {
    __half2 H = __floats2half2_rn(x, y);
    float hx = __half2float(__low2half(H));
    float hy = __half2float(__high2half(H));
    __half2 L = __floats2half2_rn(x - hx, y - hy);
    h = *(uint32_t*)&H;
    l = *(uint32_t*)&L;
}
__device__ __forceinline__ uint32_t pack_h(float x, float y) {
    __half2 H = __floats2half2_rn(x, y);
    return *(uint32_t*)&H;
}

__device__ __forceinline__ void mma_fp16(float c[4],
                                         uint32_t a0, uint32_t a1, uint32_t a2, uint32_t a3,
                                         uint32_t b0, uint32_t b1) {
    asm volatile(
        "mma.sync.aligned.m16n8k16.row.col.f32.f16.f16.f32 "
        "{%0,%1,%2,%3}, {%4,%5,%6,%7}, {%8,%9}, {%0,%1,%2,%3};"
        : "+f"(c[0]), "+f"(c[1]), "+f"(c[2]), "+f"(c[3])
        : "r"(a0), "r"(a1), "r"(a2), "r"(a3), "r"(b0), "r"(b1));
}

__device__ __forceinline__ void ldsm_x4(uint32_t& r0, uint32_t& r1, uint32_t& r2, uint32_t& r3,
                                        uint32_t addr) {
    asm volatile("ldmatrix.sync.aligned.m8n8.x4.shared.b16 {%0,%1,%2,%3}, [%4];"
                 : "=r"(r0), "=r"(r1), "=r"(r2), "=r"(r3) : "r"(addr));
}
__device__ __forceinline__ void ldsm_x4t(uint32_t& r0, uint32_t& r1, uint32_t& r2, uint32_t& r3,
                                         uint32_t addr) {
    asm volatile("ldmatrix.sync.aligned.m8n8.x4.trans.shared.b16 {%0,%1,%2,%3}, [%4];"
                 : "=r"(r0), "=r"(r1), "=r"(r2), "=r"(r3) : "r"(addr));
}

__device__ __forceinline__ void cpa16(uint32_t smem, const void* gmem) {
    asm volatile("cp.async.ca.shared.global [%0], [%1], 16;" :: "r"(smem), "l"(gmem));
}
__device__ __forceinline__ void cpa_commit() { asm volatile("cp.async.commit_group;"); }
template <int N>
__device__ __forceinline__ void cpa_wait() { asm volatile("cp.async.wait_group %0;" :: "n"(N)); }

// ---------------------------------------------------------------------------
// fp16 plane GEMM. 512 threads, 16 warps (4x4 of 32x32 warp tiles).
// PASSES=3: A,B hi+lo planes, 3 MMAs (hh,hl,lh). PASSES=1: hi planes only.
// Output: Ch!=null -> fp16 plane store (+ lo if Cl); splitk>1 -> fp32
// atomicAdd; else fp32 store. Calt: merged logits (z in [2,4) -> +selOff).
// Sub-tile layout (16KB): A at +0 (plane*4096 + m*32 + swz16);
//                         B at +8192 (TB same; NN plane*4096 + k*256 + swz16).
// ---------------------------------------------------------------------------
template <bool TB, int PASSES>
__global__ __launch_bounds__(NTH, 1) void bf_gemm(
    const fp16* __restrict__ Ah, const fp16* __restrict__ Al,
    const fp16* __restrict__ Bh, const fp16* __restrict__ Bl,
    float* __restrict__ C, float* __restrict__ Calt,
    fp16* __restrict__ Ch, fp16* __restrict__ Cl,
    int K, int lda, int ldb, int ldc,
    long long sA, long long sB, long long sC,
    float alpha, const float* __restrict__ bias, int splitk, int selOff)
{
    int zb = blockIdx.z / splitk;
    const int kchunk = blockIdx.z % splitk;
    if (Calt) {
        int sel = zb >> 1;
        zb &= 1;
        if (sel) { Ah += selOff; Al += selOff; Bh += selOff; Bl += selOff; C = Calt; }
    }
    const int kc = K / splitk;
    const int kbeg = kchunk * kc;

    Ah += (long long)zb * sA; if (PASSES == 3) Al += (long long)zb * sA;
    Bh += (long long)zb * sB; if (PASSES == 3) Bl += (long long)zb * sB;
    if (C) C += (long long)zb * sC;
    if (Ch) { Ch += (long long)zb * sC; if (Cl) Cl += (long long)zb * sC; }

    const int brow = blockIdx.y * BM;
    const int bcol = blockIdx.x * BN;
    const int t = threadIdx.x;
    const int lane = t & 31;
    const int wid = t >> 5;
    const int wm = (wid >> 2) * 32;
    const int wn = (wid & 3) * 32;
    const int q = lane & 3;
    const int r = lane >> 2;
    const int lg = lane >> 3;
    const int lr = lane & 7;

    extern __shared__ __align__(128) char sm[];
    const uint32_t sm0 = (uint32_t)__cvta_generic_to_shared(sm);

    float acc[2][4][4];
#pragma unroll
    for (int i = 0; i < 2; i++)
#pragma unroll
        for (int j = 0; j < 4; j++)
#pragma unroll
            for (int c = 0; c < 4; c++) acc[i][j][c] = 0.f;

    // cp.async: per sub-tile, 512 16B-chunks per operand (hi+lo) or 256 (hi).
    const int pl_  = t >> 8;
    const int rem_ = t & 255;
    auto load_stage = [&](int st, int k0) {
        uint32_t sbase = sm0 + (uint32_t)(st * STAGE_BYTES);
#pragma unroll
        for (int sub = 0; sub < 2; sub++) {
            uint32_t base = sbase + (uint32_t)(sub * SUB_BYTES);
            int ks = k0 + sub * 16;
            if (PASSES == 3 || pl_ == 0) {
                {
                    int m = rem_ >> 1, half = rem_ & 1;
                    const fp16* src = (pl_ ? Al : Ah) + (long long)(brow + m) * lda + ks + half * 8;
                    cpa16(base + (uint32_t)(pl_ * 4096 + m * 32 + ((half ^ ((m >> 2) & 1)) * 16)), src);
                }
                if (TB) {
                    int n = rem_ >> 1, half = rem_ & 1;
                    const fp16* src = (pl_ ? Bl : Bh) + (long long)(bcol + n) * ldb + ks + half * 8;
                    cpa16(base + (uint32_t)(8192 + pl_ * 4096 + n * 32 + ((half ^ ((n >> 2) & 1)) * 16)), src);
                } else {
                    int kk = rem_ >> 4, j = rem_ & 15;
                    const fp16* src = (pl_ ? Bl : Bh) + (long long)(ks + kk) * ldb + bcol + j * 8;
                    cpa16(base + (uint32_t)(8192 + pl_ * 4096 + kk * 256 + ((j ^ (kk & 7)) * 16)), src);
                }
            }
        }
        cpa_commit();
    };

    auto compute_sub = [&](uint32_t base) {
        const int NPL = (PASSES == 3) ? 2 : 1;
        uint32_t Bf[2][4][2];
#pragma unroll
        for (int pl = 0; pl < NPL; pl++) {
#pragma unroll
            for (int pair = 0; pair < 2; pair++) {
                int nl = pair * 2, nh = pair * 2 + 1;
                if (TB) {
                    int row = wn + pair * 16 + lr + (lg & 1) * 8;
                    int half = lg >> 1;
                    uint32_t a = base + (uint32_t)(8192 + pl * 4096 + row * 32 +
                                                   ((half ^ ((row >> 2) & 1)) * 16));
                    ldsm_x4(Bf[pl][nl][0], Bf[pl][nh][0], Bf[pl][nl][1], Bf[pl][nh][1], a);
                } else {
                    int krow = lr + (lg & 1) * 8;
                    int j = (wn >> 3) + pair * 2 + (lg >> 1);
                    uint32_t a = base + (uint32_t)(8192 + pl * 4096 + krow * 256 +
                                                   ((j ^ (krow & 7)) * 16));
                    ldsm_x4t(Bf[pl][nl][0], Bf[pl][nl][1], Bf[pl][nh][0], Bf[pl][nh][1], a);
                }
            }
        }
#pragma unroll
        for (int mt = 0; mt < 2; mt++) {
            int row = wm + mt * 16 + lr + (lg & 1) * 8;
            int half = lg >> 1;
            uint32_t swz = (uint32_t)((half ^ ((row >> 2) & 1)) * 16);
            uint32_t Ah0, Ah1, Ah2, Ah3;
            ldsm_x4(Ah0, Ah1, Ah2, Ah3, base + (uint32_t)(row * 32) + swz);
            if (PASSES == 3) {
                uint32_t Al0, Al1, Al2, Al3;
                ldsm_x4(Al0, Al1, Al2, Al3, base + (uint32_t)(4096 + row * 32) + swz);
#pragma unroll
                for (int nt = 0; nt < 4; nt++) {
                    mma_fp16(acc[mt][nt], Ah0, Ah1, Ah2, Ah3, Bf[0][nt][0], Bf[0][nt][1]);
                    mma_fp16(acc[mt][nt], Ah0, Ah1, Ah2, Ah3, Bf[1][nt][0], Bf[1][nt][1]);
                    mma_fp16(acc[mt][nt], Al0, Al1, Al2, Al3, Bf[0][nt][0], Bf[0][nt][1]);
                }
            } else {
#pragma unroll
                for (int nt = 0; nt < 4; nt++)
                    mma_fp16(acc[mt][nt], Ah0, Ah1, Ah2, Ah3, Bf[0][nt][0], Bf[0][nt][1]);
            }
        }
    };

    const int nIter = kc / BKS;
    load_stage(0, kbeg);
    if (nIter > 1) load_stage(1, kbeg + BKS);

    for (int it = 0; it < nIter; it++) {
        if (it + 1 < nIter) cpa_wait<1>(); else cpa_wait<0>();
        __syncthreads();
        if (it + 2 < nIter) load_stage((it + 2) % NSTAGE, kbeg + (it + 2) * BKS);

        uint32_t sbase = sm0 + (uint32_t)((it % NSTAGE) * STAGE_BYTES);
        compute_sub(sbase);
        compute_sub(sbase + SUB_BYTES);
        __syncthreads();
    }

    // ---- epilogue ----
#pragma unroll
    for (int mt = 0; mt < 2; mt++) {
#pragma unroll
        for (int nt = 0; nt < 4; nt++) {
            int row = brow + wm + mt * 16 + r;
            int col = bcol + wn + nt * 8 + 2 * q;
            float b0 = 0.f, b1 = 0.f;
            if (bias && kchunk == 0) { b0 = bias[col]; b1 = bias[col + 1]; }
            float v0 = alpha * acc[mt][nt][0] + b0;
            float v1 = alpha * acc[mt][nt][1] + b1;
            float v2 = alpha * acc[mt][nt][2] + b0;
            float v3 = alpha * acc[mt][nt][3] + b1;
            if (Ch) {
                if (Cl) {
                    uint32_t h, l;
                    split2(v0, v1, h, l);
                    *(uint32_t*)&Ch[(long long)row * ldc + col] = h;
                    *(uint32_t*)&Cl[(long long)row * ldc + col] = l;
                    split2(v2, v3, h, l);
                    *(uint32_t*)&Ch[(long long)(row + 8) * ldc + col] = h;
                    *(uint32_t*)&Cl[(long long)(row + 8) * ldc + col] = l;
                } else {
                    *(uint32_t*)&Ch[(long long)row * ldc + col] = pack_h(v0, v1);
                    *(uint32_t*)&Ch[(long long)(row + 8) * ldc + col] = pack_h(v2, v3);
                }
            } else if (splitk > 1) {
                atomicAdd(&C[(long long)row * ldc + col], v0);
                atomicAdd(&C[(long long)row * ldc + col + 1], v1);
                atomicAdd(&C[(long long)(row + 8) * ldc + col], v2);
                atomicAdd(&C[(long long)(row + 8) * ldc + col + 1], v3);
            } else {
                *(float2*)&C[(long long)row * ldc + col] = make_float2(v0, v1);
                *(float2*)&C[(long long)(row + 8) * ldc + col] = make_float2(v2, v3);
            }
        }
    }
}

// ---------------------------------------------------------------------------
__global__ void split_kernel(const float4* __restrict__ src,
                             uint2* __restrict__ h, uint2* __restrict__ l, int n4)
{
    int i = blockIdx.x * blockDim.x + threadIdx.x;
    if (i < n4) {
        float4 v = src[i];
        uint32_t h0, l0, h1, l1;
        split2(v.x, v.y, h0, l0);
        split2(v.z, v.w, h1, l1);
        h[i] = make_uint2(h0, h1);
        l[i] = make_uint2(l0, l1);
    }
}

__global__ void lambda_kernel(const float* __restrict__ lq1, const float* __restrict__ lk1,
                              const float* __restrict__ lq2, const float* __restrict__ lk2)
{
    if (threadIdx.x == 0) {
        float d1 = 0.f, d2 = 0.f;
        for (int i = 0; i < 64; i++) {
            d1 += lq1[i] * lk1[i];
            d2 += lq2[i] * lk2[i];
        }
        g_lambda = expf(d1) - expf(d2) + (0.8f - 0.6f * expf(-0.3f * 0.0f));
    }
}

// cvec[n] = bo[n] + (1-lam) * sum_k bv[k]*Wo[k,n]; one block per n.
__global__ __launch_bounds__(256) void cvec_kernel(
    const float* __restrict__ bv, const float* __restrict__ Wo,
    const float* __restrict__ bo)
{
    const int n = blockIdx.x;
    const int t = threadIdx.x;
    float s = 0.f;
    for (int k = t; k < 8192; k += 256)
        s += bv[k] * Wo[(long long)k * 512 + n];
    __shared__ float red[256];
    red[t] = s;
    __syncthreads();
    for (int o = 128; o; o >>= 1) {
        if (t < o) red[t] += red[t + o];
        __syncthreads();
    }
    if (t == 0) g_cvec[n] = bo[n] + (1.f - g_lambda) * red[0];
}

// ---------------------------------------------------------------------------
// Fused dual softmax + differential combine; writes single fp16 plane.
// ---------------------------------------------------------------------------
__global__ __launch_bounds__(256) void softmax_diff_kernel(
    const float* __restrict__ l1, const float* __restrict__ l2,
    fp16* __restrict__ dh)
{
    long long row = blockIdx.x;
    const float* r1 = l1 + row * 2048;
    const float* r2 = l2 + row * 2048;
    const int t = threadIdx.x;
    const int lane = t & 31, warp = t >> 5;

    float v1[8], v2[8];
    *(float4*)&v1[0] = *(const float4*)&r1[t * 8];
    *(float4*)&v1[4] = *(const float4*)&r1[t * 8 + 4];
    *(float4*)&v2[0] = *(const float4*)&r2[t * 8];
    *(float4*)&v2[4] = *(const float4*)&r2[t * 8 + 4];

    float m1 = -1e30f, m2 = -1e30f;
#pragma unroll
    for (int i = 0; i < 8; i++) {
        m1 = fmaxf(m1, v1[i]);
        m2 = fmaxf(m2, v2[i]);
    }
#pragma unroll
    for (int o = 16; o; o >>= 1) {
        m1 = fmaxf(m1, __shfl_xor_sync(0xffffffffu, m1, o));
        m2 = fmaxf(m2, __shfl_xor_sync(0xffffffffu, m2, o));
    }
    __shared__ float s1[8], s2[8];
    if (lane == 0) { s1[warp] = m1; s2[warp] = m2; }
    __syncthreads();
    m1 = s1[0]; m2 = s2[0];
#pragma unroll
    for (int w = 1; w < 8; w++) {
        m1 = fmaxf(m1, s1[w]);
        m2 = fmaxf(m2, s2[w]);
    }

    float e1[8], e2[8];
    float sum1 = 0.f, sum2 = 0.f;
#pragma unroll
    for (int i = 0; i < 8; i++) {
        e1[i] = __expf(v1[i] - m1);
        e2[i] = __expf(v2[i] - m2);
        sum1 += e1[i];
        sum2 += e2[i];
    }
#pragma unroll
    for (int o = 16; o; o >>= 1) {
        sum1 += __shfl_xor_sync(0xffffffffu, sum1, o);
        sum2 += __shfl_xor_sync(0xffffffffu, sum2, o);
    }
    __syncthreads();
    if (lane == 0) { s1[warp] = sum1; s2[warp] = sum2; }
    __syncthreads();
    sum1 = 0.f; sum2 = 0.f;
#pragma unroll
    for (int w = 0; w < 8; w++) { sum1 += s1[w]; sum2 += s2[w]; }

    const float inv1 = 1.f / sum1;
    const float inv2 = g_lambda / sum2;
    uint4 hv;
    hv.x = pack_h(e1[0] * inv1 - e2[0] * inv2, e1[1] * inv1 - e2[1] * inv2);
    hv.y = pack_h(e1[2] * inv1 - e2[2] * inv2, e1[3] * inv1 - e2[3] * inv2);
    hv.z = pack_h(e1[4] * inv1 - e2[4] * inv2, e1[5] * inv1 - e2[5] * inv2);
    hv.w = pack_h(e1[6] * inv1 - e2[6] * inv2, e1[7] * inv1 - e2[7] * inv2);
    *(uint4*)&dh[row * 2048 + t * 8] = hv;
}

// ---------------------------------------------------------------------------
extern "C" void kernel_launch(void* const* d_in, const int* in_sizes, int n_in,
                              void* d_out, int out_size)
{
    const float* x    = (const float*)d_in[0];
    const float* Wqkv = (const float*)d_in[1];
    const float* bqkv = (const float*)d_in[2];
    const float* Wv   = (const float*)d_in[3];
    const float* bv   = (const float*)d_in[4];
    const float* Wo   = (const float*)d_in[5];
    const float* bo   = (const float*)d_in[6];
    const float* lq1  = (const float*)d_in[7];
    const float* lk1  = (const float*)d_in[8];
    const float* lq2  = (const float*)d_in[9];
    const float* lk2  = (const float*)d_in[10];
    float* out = (float*)d_out;

    cudaFuncSetAttribute(bf_gemm<false, 3>, cudaFuncAttributeMaxDynamicSharedMemorySize, DSMEM_BYTES);
    cudaFuncSetAttribute(bf_gemm<true, 3>,  cudaFuncAttributeMaxDynamicSharedMemorySize, DSMEM_BYTES);
    cudaFuncSetAttribute(bf_gemm<false, 1>, cudaFuncAttributeMaxDynamicSharedMemorySize, DSMEM_BYTES);

    float *Mm, *l1, *l2, *cvec;
    fp16 *xh, *xl, *wqh, *wql, *wvh, *wvl, *woh, *wol;
    fp16 *qh, *ql, *mh, *ml, *vph, *dh;
    cudaGetSymbolAddress((void**)&Mm,  g_M);
    cudaGetSymbolAddress((void**)&l1,  g_l1);
    cudaGetSymbolAddress((void**)&l2,  g_l2);
    cudaGetSymbolAddress((void**)&cvec, g_cvec);
    cudaGetSymbolAddress((void**)&xh,  g_xh);   cudaGetSymbolAddress((void**)&xl,  g_xl);
    cudaGetSymbolAddress((void**)&wqh, g_wqh);  cudaGetSymbolAddress((void**)&wql, g_wql);
    cudaGetSymbolAddress((void**)&wvh, g_wvh);  cudaGetSymbolAddress((void**)&wvl, g_wvl);
    cudaGetSymbolAddress((void**)&woh, g_woh);  cudaGetSymbolAddress((void**)&wol, g_wol);
    cudaGetSymbolAddress((void**)&qh,  g_qh);   cudaGetSymbolAddress((void**)&ql,  g_ql);
    cudaGetSymbolAddress((void**)&mh,  g_mh);   cudaGetSymbolAddress((void**)&ml,  g_ml);
    cudaGetSymbolAddress((void**)&vph, g_vph);
    cudaGetSymbolAddress((void**)&dh,  g_dh);

    const long long SQ  = 2048LL * 1024;
    const long long SL  = 2048LL * 2048;
    const long long SV  = 2048LL * 512;

    // launches 1-5 (so ncu -s 5 profiles the qkv GEMM at #6)
    lambda_kernel<<<1, 32>>>(lq1, lk1, lq2, lk2);
    split_kernel<<<2048, 256>>>((const float4*)x,    (uint2*)xh,  (uint2*)xl,  4096 * 512 / 4);
    split_kernel<<<512,  256>>>((const float4*)Wqkv, (uint2*)wqh, (uint2*)wql, 512 * 1024 / 4);
    split_kernel<<<4096, 256>>>((const float4*)Wv,   (uint2*)wvh, (uint2*)wvl, 512 * 8192 / 4);
    split_kernel<<<4096, 256>>>((const float4*)Wo,   (uint2*)woh, (uint2*)wol, 8192 * 512 / 4);

    // 6) qkv = x @ Wqkv + bqkv -> planes  [4096,1024]   (3-pass)
    bf_gemm<false, 3><<<dim3(8, 32, 1), NTH, DSMEM_BYTES>>>(
        xh, xl, wqh, wql, nullptr, nullptr, qh, ql,
        512, 512, 1024, 1024, 0, 0, 0, 1.f, bqkv, 1, 0);

    // M = Wv @ Wo  (fp32, splitK=16), then split to planes
    cudaMemsetAsync(Mm, 0, 512 * 512 * sizeof(float));
    bf_gemm<false, 3><<<dim3(4, 4, 16), NTH, DSMEM_BYTES>>>(
        wvh, wvl, woh, wol, Mm, nullptr, nullptr, nullptr,
        8192, 8192, 512, 512, 0, 0, 0, 1.f, nullptr, 16, 0);
    split_kernel<<<256, 256>>>((const float4*)Mm, (uint2*)mh, (uint2*)ml, 512 * 512 / 4);

    // V' = x @ M -> single fp16 plane  [4096,512]   (3-pass compute)
    bf_gemm<false, 3><<<dim3(4, 32, 1), NTH, DSMEM_BYTES>>>(
        xh, xl, mh, ml, nullptr, nullptr, vph, nullptr,
        512, 512, 512, 512, 0, 0, 0, 1.f, nullptr, 1, 0);

    // logits merged (z=0,1 -> l1 via Q1/K1; z=2,3 -> l2 via +256 offset)
    bf_gemm<true, 3><<<dim3(16, 16, 4), NTH, DSMEM_BYTES>>>(
        qh + 0, ql + 0, qh + 512, ql + 512, l1, l2, nullptr, nullptr,
        256, 1024, 1024, 2048, SQ, SQ, SL, 0.125f, nullptr, 1, 256);

    // cvec (needed only before final)
    cvec_kernel<<<512, 256>>>(bv, Wo, bo);

    // diff = softmax(l1) - lam*softmax(l2) -> single fp16 plane
    softmax_diff_kernel<<<4096, 256>>>(l1, l2, dh);

    // out = diff @ V' + cvec  (fp32, 1-pass fp16, splitK=4)
    cudaMemsetAsync(out, 0, 2 * 2048 * 512 * sizeof(float));
    bf_gemm<false, 1><<<dim3(4, 16, 8), NTH, DSMEM_BYTES>>>(
        dh, nullptr, vph, nullptr, out, nullptr, nullptr, nullptr,
        2048, 2048, 512, 512, SL, SV, SV, 1.f, cvec, 4, 0);
}